// round 4
// baseline (speedup 1.0000x reference)
#include <cuda_runtime.h>
#include <math.h>

// ---------------- problem constants ----------------
constexpr int kNS   = 25;            // support clips (WAY*SHOT)
constexpr int kNQ   = 500;           // queries
constexpr int kNALL = kNS + kNQ;     // 525
constexpr int kSEQ  = 8;
constexpr int kFEAT = 2048;
constexpr int kD    = 1152;          // DOUT
constexpr int kT    = 28;            // C(8,2)
constexpr int kWAY  = 5;
constexpr int kKU   = 140;           // SHOT * T
constexpr int kKUP  = 144;           // padded
constexpr int kRX   = kNALL * kSEQ;  // 4200 per-frame rows
constexpr int kPC   = 4 * kD;        // 4608 = Ktop|Kbot|Vtop|Vbot
constexpr int kQR   = kNQ * kT;      // 14000 query-tuple rows
constexpr int kNTR  = kNALL * kT;    // 14700 all-tuple rows

// ---------------- scratch (device globals: no allocation allowed) ----------------
__device__ float d_X[(size_t)kRX * kFEAT];       // 34.4 MB  frames + PE
__device__ float d_W[(size_t)kFEAT * kPC];       // 37.7 MB  concatenated weights
__device__ float d_P[(size_t)kRX * kPC];         // 77.4 MB  per-frame projections
__device__ float d_qk[(size_t)kNTR * kD];        // 67.7 MB  LN'd K features (support first)
__device__ float d_qv[(size_t)kNTR * kD];        // 67.7 MB  V features
__device__ float d_attn[(size_t)kWAY * kQR * kKUP]; // 40.3 MB scores -> attn (padded 144)

// tuple table: combinations(range(8),2) lexicographic
__constant__ int c_ti[kT] = {0,0,0,0,0,0,0,1,1,1,1,1,1,2,2,2,2,2,3,3,3,3,4,4,4,5,5,6};
__constant__ int c_tj[kT] = {1,2,3,4,5,6,7,2,3,4,5,6,7,3,4,5,6,7,4,5,6,7,5,6,7,6,7,7};

// ---------------- packed f32x2 helpers (Blackwell: doubles fp32 FMA rate) ----------------
typedef unsigned long long u64;
__device__ __forceinline__ u64 pk2(float lo, float hi) {
    u64 r; asm("mov.b64 %0,{%1,%2};" : "=l"(r) : "f"(lo), "f"(hi)); return r;
}
__device__ __forceinline__ void fma2(u64& d, u64 a, u64 b) {
    asm("fma.rn.f32x2 %0,%1,%2,%0;" : "+l"(d) : "l"(a), "l"(b));
}
__device__ __forceinline__ float2 upk2(u64 v) {
    float2 f; asm("mov.b64 {%0,%1},%2;" : "=f"(f.x), "=f"(f.y) : "l"(v)); return f;
}

// ---------------- K0a: X = input frames + positional encoding ----------------
__global__ void k_build_x(const float* __restrict__ sup, const float* __restrict__ qry) {
    int r = blockIdx.x;                 // 0..4199 = n*8 + f
    int n = r >> 3, f = r & 7;
    const float* src = (n < kNS) ? (sup + (size_t)r * kFEAT)
                                 : (qry + (size_t)(r - kNS * kSEQ) * kFEAT);
    float* dst = d_X + (size_t)r * kFEAT;
    const float cc = -logf(10000.0f) / (float)kFEAT;
    float pf = (float)f;
    for (int d = threadIdx.x; d < kFEAT; d += blockDim.x) {
        int j2 = d & ~1;                         // 2*(d/2)
        float dv = expf(cc * (float)j2);
        float v  = pf * dv;
        float pe = (d & 1) ? cosf(v) : sinf(v);
        dst[d] = src[d] + pe;
    }
}

// ---------------- K0b: Wcat = [k_w_top | k_w_bot | v_w_top | v_w_bot] ----------------
__global__ void k_build_w(const float* __restrict__ kw, const float* __restrict__ vw) {
    int k = blockIdx.x;                 // 0..2047
    float* dst = d_W + (size_t)k * kPC;
    const float* k0 = kw + (size_t)k * kD;
    const float* k1 = kw + (size_t)(k + kFEAT) * kD;
    const float* v0 = vw + (size_t)k * kD;
    const float* v1 = vw + (size_t)(k + kFEAT) * kD;
    for (int d = threadIdx.x; d < kD; d += blockDim.x) {
        dst[d]        = k0[d];
        dst[kD + d]   = k1[d];
        dst[2*kD + d] = v0[d];
        dst[3*kD + d] = v1[d];
    }
}

// ---------------- K1: P[4200,4608] = X[4200,2048] @ W[2048,4608] ----------------
__global__ __launch_bounds__(256) void k_gemm1() {
    __shared__ __align__(16) float As[8][128];
    __shared__ __align__(16) float Bs[8][128];
    const int tid = threadIdx.x;
    const int bm = blockIdx.y * 128;
    const int bn = blockIdx.x * 128;
    const int aRow = tid >> 1, aCol = (tid & 1) << 2;
    const int bRow = tid >> 5, bCol = (tid & 31) << 2;
    const int ty = tid >> 4, tx = tid & 15;
    const bool aOk = (bm + aRow) < kRX;
    const float* Ag = d_X + (size_t)(bm + aRow) * kFEAT + aCol;
    const float* Bg = d_W + (size_t)bRow * kPC + bn + bCol;
    u64 acc[4][8];
    #pragma unroll
    for (int u = 0; u < 4; u++)
        #pragma unroll
        for (int j = 0; j < 8; j++) acc[u][j] = 0ull;

    for (int k0 = 0; k0 < kFEAT; k0 += 8) {
        float4 av = aOk ? *(const float4*)(Ag + k0) : make_float4(0.f,0.f,0.f,0.f);
        float4 bv = *(const float4*)(Bg + (size_t)k0 * kPC);
        As[aCol + 0][aRow] = av.x; As[aCol + 1][aRow] = av.y;
        As[aCol + 2][aRow] = av.z; As[aCol + 3][aRow] = av.w;
        *(float4*)&Bs[bRow][bCol] = bv;
        __syncthreads();
        #pragma unroll
        for (int kk = 0; kk < 8; kk++) {
            const u64* ap = (const u64*)&As[kk][ty << 3];
            u64 a2[4] = {ap[0], ap[1], ap[2], ap[3]};
            float bsv[8];
            *(float4*)bsv       = *(const float4*)&Bs[kk][tx << 3];
            *(float4*)(bsv + 4) = *(const float4*)&Bs[kk][(tx << 3) + 4];
            u64 b2[8];
            #pragma unroll
            for (int j = 0; j < 8; j++) b2[j] = pk2(bsv[j], bsv[j]);
            #pragma unroll
            for (int u = 0; u < 4; u++)
                #pragma unroll
                for (int j = 0; j < 8; j++) fma2(acc[u][j], a2[u], b2[j]);
        }
        __syncthreads();
    }
    #pragma unroll
    for (int u = 0; u < 4; u++) {
        float r0[8], r1[8];
        #pragma unroll
        for (int j = 0; j < 8; j++) { float2 p = upk2(acc[u][j]); r0[j] = p.x; r1[j] = p.y; }
        int row0 = bm + (ty << 3) + 2 * u;
        if (row0 < kRX) {
            float* cp = d_P + (size_t)row0 * kPC + bn + (tx << 3);
            *(float4*)cp = *(float4*)r0; *(float4*)(cp + 4) = *(float4*)(r0 + 4);
        }
        if (row0 + 1 < kRX) {
            float* cp = d_P + (size_t)(row0 + 1) * kPC + bn + (tx << 3);
            *(float4*)cp = *(float4*)r1; *(float4*)(cp + 4) = *(float4*)(r1 + 4);
        }
    }
}

// ---------------- K2: tuple combine + bias + LayerNorm(K) ----------------
__global__ __launch_bounds__(256) void k_combine(const float* __restrict__ kb,
                                                 const float* __restrict__ vb,
                                                 const float* __restrict__ g,
                                                 const float* __restrict__ be) {
    int b = blockIdx.x;                 // n*28 + t
    int n = b / kT, t = b - n * kT;
    const float* Pi = d_P + (size_t)(n * kSEQ + c_ti[t]) * kPC;
    const float* Pj = d_P + (size_t)(n * kSEQ + c_tj[t]) * kPC;
    int tid = threadIdx.x;
    float kv[5];
    float s = 0.f, ss = 0.f;
    #pragma unroll
    for (int u = 0; u < 5; u++) {
        int d = tid + (u << 8);
        if (d < kD) {
            float val = Pi[d] + Pj[kD + d] + kb[d];
            kv[u] = val; s += val; ss += val * val;
            d_qv[(size_t)b * kD + d] = Pi[2*kD + d] + Pj[3*kD + d] + vb[d];
        }
    }
    #pragma unroll
    for (int o = 16; o; o >>= 1) {
        s  += __shfl_xor_sync(0xffffffffu, s, o);
        ss += __shfl_xor_sync(0xffffffffu, ss, o);
    }
    __shared__ float shs[8], shss[8];
    __shared__ float sh_mu, sh_inv;
    if ((tid & 31) == 0) { shs[tid >> 5] = s; shss[tid >> 5] = ss; }
    __syncthreads();
    if (tid == 0) {
        float S = 0.f, SS = 0.f;
        #pragma unroll
        for (int w = 0; w < 8; w++) { S += shs[w]; SS += shss[w]; }
        float mu = S / (float)kD;
        sh_mu = mu;
        sh_inv = rsqrtf(SS / (float)kD - mu * mu + 1e-5f);
    }
    __syncthreads();
    float mu = sh_mu, inv = sh_inv;
    #pragma unroll
    for (int u = 0; u < 5; u++) {
        int d = tid + (u << 8);
        if (d < kD) d_qk[(size_t)b * kD + d] = (kv[u] - mu) * inv * g[d] + be[d];
    }
}

// ---------------- K3: per-class scores = Qk[14000,1152] @ Kc[140,1152]^T ----------------
__global__ __launch_bounds__(256) void k_scores() {
    const int c = blockIdx.z;
    const float* A = d_qk + (size_t)kNS * kT * kD;       // queries only
    const float* B = d_qk + (size_t)c * kKU * kD;        // class_k chunk
    float* C = d_attn + (size_t)c * kQR * kKUP;
    __shared__ __align__(16) float As[8][128];
    __shared__ __align__(16) float Bs[8][kKUP];
    const int tid = threadIdx.x;
    const int bm = blockIdx.x * 128;
    const int aRow = tid >> 1, aCol = (tid & 1) << 2;
    const int ty = tid >> 4, tx = tid & 15;              // 9 cols each
    const bool aOk = (bm + aRow) < kQR;
    u64 acc[4][9];
    #pragma unroll
    for (int u = 0; u < 4; u++)
        #pragma unroll
        for (int j = 0; j < 9; j++) acc[u][j] = 0ull;

    for (int k0 = 0; k0 < kD; k0 += 8) {
        float4 av = aOk ? *(const float4*)(A + (size_t)(bm + aRow) * kD + k0 + aCol)
                        : make_float4(0.f,0.f,0.f,0.f);
        As[aCol + 0][aRow] = av.x; As[aCol + 1][aRow] = av.y;
        As[aCol + 2][aRow] = av.z; As[aCol + 3][aRow] = av.w;
        for (int idx = tid; idx < kKUP * 8; idx += 256) {
            int nn = idx >> 3, kk = idx & 7;
            Bs[kk][nn] = (nn < kKU) ? B[(size_t)nn * kD + k0 + kk] : 0.f;
        }
        __syncthreads();
        #pragma unroll
        for (int kk = 0; kk < 8; kk++) {
            const u64* ap = (const u64*)&As[kk][ty << 3];
            u64 a2[4] = {ap[0], ap[1], ap[2], ap[3]};
            u64 b2[9];
            #pragma unroll
            for (int j = 0; j < 9; j++) { float bb = Bs[kk][tx * 9 + j]; b2[j] = pk2(bb, bb); }
            #pragma unroll
            for (int u = 0; u < 4; u++)
                #pragma unroll
                for (int j = 0; j < 9; j++) fma2(acc[u][j], a2[u], b2[j]);
        }
        __syncthreads();
    }
    const float sc = 1.0f / sqrtf((float)kD);
    #pragma unroll
    for (int u = 0; u < 4; u++) {
        int r0 = bm + (ty << 3) + 2 * u;
        #pragma unroll
        for (int j = 0; j < 9; j++) {
            float2 p = upk2(acc[u][j]);
            if (r0 < kQR)     C[(size_t)r0 * kKUP + tx * 9 + j]       = p.x * sc;
            if (r0 + 1 < kQR) C[(size_t)(r0 + 1) * kKUP + tx * 9 + j] = p.y * sc;
        }
    }
}

// ---------------- K4: softmax over 140 (one warp per row) ----------------
__global__ void k_softmax() {
    int row = (blockIdx.x << 3) + (threadIdx.x >> 5);   // 70000 rows total
    int lane = threadIdx.x & 31;
    float* p = d_attn + (size_t)row * kKUP;
    float v[5];
    float m = -1e30f;
    #pragma unroll
    for (int u = 0; u < 5; u++) {
        int i = lane + (u << 5);
        v[u] = (i < kKU) ? p[i] : -1e30f;
        m = fmaxf(m, v[u]);
    }
    #pragma unroll
    for (int o = 16; o; o >>= 1) m = fmaxf(m, __shfl_xor_sync(0xffffffffu, m, o));
    float s = 0.f;
    #pragma unroll
    for (int u = 0; u < 5; u++) {
        float e = ((lane + (u << 5)) < kKU) ? expf(v[u] - m) : 0.f;
        v[u] = e; s += e;
    }
    #pragma unroll
    for (int o = 16; o; o >>= 1) s += __shfl_xor_sync(0xffffffffu, s, o);
    float inv = 1.0f / s;
    #pragma unroll
    for (int u = 0; u < 5; u++) {
        int i = lane + (u << 5);
        if (i < kKU) p[i] = v[u] * inv;
    }
}

// ---------------- K5: fused proto = attn @ Vc, dist, logits ----------------
__global__ __launch_bounds__(288) void k_dist(const float* __restrict__ gt,
                                              const float* __restrict__ tw,
                                              float* __restrict__ out) {
    const int q = blockIdx.x, c = blockIdx.y;
    __shared__ __align__(16) float at[kKUP][kT];        // transposed attn tile
    const float* Ab = d_attn + ((size_t)c * kQR + (size_t)q * kT) * kKUP;
    const int tid = threadIdx.x;
    for (int idx = tid; idx < kT * kKUP; idx += 288) {
        int t = idx / kKUP, k = idx - t * kKUP;
        at[k][t] = Ab[idx];
    }
    __syncthreads();
    const float* Vc = d_qv + (size_t)c * kKU * kD;      // class_v: 140 x 1152
    const int d0 = tid << 2;                            // 288*4 = 1152 cols
    u64 acc[14][4];
    #pragma unroll
    for (int tp = 0; tp < 14; tp++)
        #pragma unroll
        for (int j = 0; j < 4; j++) acc[tp][j] = 0ull;

    for (int k = 0; k < kKU; k++) {
        float4 v = *(const float4*)(Vc + (size_t)k * kD + d0);
        u64 vx = pk2(v.x, v.x), vy = pk2(v.y, v.y), vz = pk2(v.z, v.z), vw = pk2(v.w, v.w);
        const u64* ap = (const u64*)&at[k][0];          // 14 (t,t+1) pairs
        #pragma unroll
        for (int tp = 0; tp < 14; tp++) {
            u64 a2 = ap[tp];
            fma2(acc[tp][0], a2, vx);
            fma2(acc[tp][1], a2, vy);
            fma2(acc[tp][2], a2, vz);
            fma2(acc[tp][3], a2, vw);
        }
    }
    const float* Qv = d_qv + (size_t)(kNS + q) * kT * kD + d0;
    float s = 0.f;
    #pragma unroll
    for (int tp = 0; tp < 14; tp++) {
        float4 qa = *(const float4*)(Qv + (size_t)(2 * tp) * kD);
        float4 qb = *(const float4*)(Qv + (size_t)(2 * tp + 1) * kD);
        float2 p0 = upk2(acc[tp][0]), p1 = upk2(acc[tp][1]);
        float2 p2 = upk2(acc[tp][2]), p3 = upk2(acc[tp][3]);
        float dd;
        dd = qa.x - p0.x; s += dd * dd;  dd = qb.x - p0.y; s += dd * dd;
        dd = qa.y - p1.x; s += dd * dd;  dd = qb.y - p1.y; s += dd * dd;
        dd = qa.z - p2.x; s += dd * dd;  dd = qb.z - p2.y; s += dd * dd;
        dd = qa.w - p3.x; s += dd * dd;  dd = qb.w - p3.y; s += dd * dd;
    }
    #pragma unroll
    for (int o = 16; o; o >>= 1) s += __shfl_xor_sync(0xffffffffu, s, o);
    __shared__ float red[9];
    if ((tid & 31) == 0) red[tid >> 5] = s;
    __syncthreads();
    if (tid == 0) {
        float S = 0.f;
        #pragma unroll
        for (int w = 0; w < 9; w++) S += red[w];
        out[q * kWAY + c] = -(S / (float)kT) * gt[0] * tw[0];
    }
}

// ---------------- launch ----------------
extern "C" void kernel_launch(void* const* d_in, const int* in_sizes, int n_in,
                              void* d_out, int out_size) {
    const float* sup = (const float*)d_in[0];
    // d_in[1] = support_labels (sorted, balanced -> reshape, unused like reference)
    const float* qry = (const float*)d_in[2];
    const float* kw  = (const float*)d_in[3];
    const float* kb  = (const float*)d_in[4];
    const float* vw  = (const float*)d_in[5];
    const float* vb  = (const float*)d_in[6];
    const float* g   = (const float*)d_in[7];
    const float* be  = (const float*)d_in[8];
    const float* gt  = (const float*)d_in[9];
    const float* tw  = (const float*)d_in[10];
    float* out = (float*)d_out;

    k_build_x<<<kRX, 256>>>(sup, qry);
    k_build_w<<<kFEAT, 256>>>(kw, vw);
    k_gemm1<<<dim3(kPC / 128, (kRX + 127) / 128), 256>>>();
    k_combine<<<kNTR, 256>>>(kb, vb, g, be);
    k_scores<<<dim3((kQR + 127) / 128, 1, kWAY), 256>>>();
    k_softmax<<<(kWAY * kQR) / 8, 256>>>();
    k_dist<<<dim3(kNQ, kWAY), 288>>>(gt, tw, out);
}

// round 5
// speedup vs baseline: 7.3421x; 7.3421x over previous
#include <cuda_runtime.h>
#include <math.h>

// ---------------- problem constants ----------------
constexpr int kNS   = 25;            // support clips (WAY*SHOT)
constexpr int kNQ   = 500;           // queries
constexpr int kNALL = kNS + kNQ;     // 525
constexpr int kSEQ  = 8;
constexpr int kFEAT = 2048;
constexpr int kD    = 1152;          // DOUT
constexpr int kT    = 28;            // C(8,2)
constexpr int kWAY  = 5;
constexpr int kKU   = 140;           // SHOT * T
constexpr int kKUP  = 144;           // padded
constexpr int kRX   = kNALL * kSEQ;  // 4200 per-frame rows
constexpr int kPC   = 4 * kD;        // 4608 = Ktop|Kbot|Vtop|Vbot
constexpr int kQR   = kNQ * kT;      // 14000 query-tuple rows
constexpr int kNTR  = kNALL * kT;    // 14700 all-tuple rows

// ---------------- scratch (device globals: no allocation allowed) ----------------
__device__ float d_X[(size_t)kRX * kFEAT];
__device__ float d_W[(size_t)kFEAT * kPC];
__device__ float d_P[(size_t)kRX * kPC];
__device__ float d_qk[(size_t)kNTR * kD];
__device__ float d_qv[(size_t)kNTR * kD];
__device__ float d_attn[(size_t)kWAY * kQR * kKUP];

// tuple table: combinations(range(8),2) lexicographic
__constant__ int c_ti[kT] = {0,0,0,0,0,0,0,1,1,1,1,1,1,2,2,2,2,2,3,3,3,3,4,4,4,5,5,6};
__constant__ int c_tj[kT] = {1,2,3,4,5,6,7,2,3,4,5,6,7,3,4,5,6,7,4,5,6,7,5,6,7,6,7,7};

// ---------------- packed f32x2 helpers ----------------
typedef unsigned long long u64;
__device__ __forceinline__ u64 pk2(float lo, float hi) {
    u64 r; asm("mov.b64 %0,{%1,%2};" : "=l"(r) : "f"(lo), "f"(hi)); return r;
}
__device__ __forceinline__ void fma2(u64& d, u64 a, u64 b) {
    asm("fma.rn.f32x2 %0,%1,%2,%0;" : "+l"(d) : "l"(a), "l"(b));
}
__device__ __forceinline__ float2 upk2(u64 v) {
    float2 f; asm("mov.b64 {%0,%1},%2;" : "=f"(f.x), "=f"(f.y) : "l"(v)); return f;
}

// ---------------- K0a: X = input frames + positional encoding ----------------
__global__ void k_build_x(const float* __restrict__ sup, const float* __restrict__ qry) {
    int r = blockIdx.x;                 // 0..4199 = n*8 + f
    int n = r >> 3, f = r & 7;
    const float* src = (n < kNS) ? (sup + (size_t)r * kFEAT)
                                 : (qry + (size_t)(r - kNS * kSEQ) * kFEAT);
    float* dst = d_X + (size_t)r * kFEAT;
    const float cc = -logf(10000.0f) / (float)kFEAT;
    float pf = (float)f;
    for (int d = threadIdx.x; d < kFEAT; d += blockDim.x) {
        int j2 = d & ~1;
        float dv = expf(cc * (float)j2);
        float v  = pf * dv;
        float pe = (d & 1) ? cosf(v) : sinf(v);
        dst[d] = src[d] + pe;
    }
}

// ---------------- K0b: Wcat = [k_w_top | k_w_bot | v_w_top | v_w_bot] ----------------
__global__ void k_build_w(const float* __restrict__ kw, const float* __restrict__ vw) {
    int k = blockIdx.x;                 // 0..2047
    float* dst = d_W + (size_t)k * kPC;
    const float* k0 = kw + (size_t)k * kD;
    const float* k1 = kw + (size_t)(k + kFEAT) * kD;
    const float* v0 = vw + (size_t)k * kD;
    const float* v1 = vw + (size_t)(k + kFEAT) * kD;
    for (int d = threadIdx.x; d < kD; d += blockDim.x) {
        dst[d]        = k0[d];
        dst[kD + d]   = k1[d];
        dst[2*kD + d] = v0[d];
        dst[3*kD + d] = v1[d];
    }
}

// ---------------- K1: P[4200,4608] = X[4200,2048] @ W[2048,4608] ----------------
// Per-thread columns are strided (tx + 16*j) -> conflict-free LDS.32 B reads.
__global__ __launch_bounds__(256) void k_gemm1() {
    __shared__ __align__(16) float As[8][128];
    __shared__ __align__(16) float Bs[8][128];
    const int tid = threadIdx.x;
    const int bm = blockIdx.y * 128;
    const int bn = blockIdx.x * 128;
    const int aRow = tid >> 1, aCol = (tid & 1) << 2;
    const int bRow = tid >> 5, bCol = (tid & 31) << 2;
    const int ty = tid >> 4, tx = tid & 15;
    const bool aOk = (bm + aRow) < kRX;
    const float* Ag = d_X + (size_t)(bm + aRow) * kFEAT + aCol;
    const float* Bg = d_W + (size_t)bRow * kPC + bn + bCol;
    u64 acc[4][8];
    #pragma unroll
    for (int u = 0; u < 4; u++)
        #pragma unroll
        for (int j = 0; j < 8; j++) acc[u][j] = 0ull;

    for (int k0 = 0; k0 < kFEAT; k0 += 8) {
        float4 av = aOk ? *(const float4*)(Ag + k0) : make_float4(0.f,0.f,0.f,0.f);
        float4 bv = *(const float4*)(Bg + (size_t)k0 * kPC);
        As[aCol + 0][aRow] = av.x; As[aCol + 1][aRow] = av.y;
        As[aCol + 2][aRow] = av.z; As[aCol + 3][aRow] = av.w;
        *(float4*)&Bs[bRow][bCol] = bv;
        __syncthreads();
        #pragma unroll
        for (int kk = 0; kk < 8; kk++) {
            const u64* ap = (const u64*)&As[kk][ty << 3];
            u64 a2[4] = {ap[0], ap[1], ap[2], ap[3]};
            u64 b2[8];
            #pragma unroll
            for (int j = 0; j < 8; j++) {
                float bb = Bs[kk][tx + (j << 4)];   // bank-conflict-free
                b2[j] = pk2(bb, bb);
            }
            #pragma unroll
            for (int u = 0; u < 4; u++)
                #pragma unroll
                for (int j = 0; j < 8; j++) fma2(acc[u][j], a2[u], b2[j]);
        }
        __syncthreads();
    }
    #pragma unroll
    for (int u = 0; u < 4; u++) {
        int row0 = bm + (ty << 3) + 2 * u;
        float* cp0 = d_P + (size_t)row0 * kPC + bn + tx;
        float* cp1 = cp0 + kPC;
        bool ok0 = row0 < kRX, ok1 = (row0 + 1) < kRX;
        #pragma unroll
        for (int j = 0; j < 8; j++) {
            float2 p = upk2(acc[u][j]);
            if (ok0) cp0[j << 4] = p.x;
            if (ok1) cp1[j << 4] = p.y;
        }
    }
}

// ---------------- K2: tuple combine + bias + LayerNorm(K) ----------------
__global__ __launch_bounds__(256) void k_combine(const float* __restrict__ kb,
                                                 const float* __restrict__ vb,
                                                 const float* __restrict__ g,
                                                 const float* __restrict__ be) {
    int b = blockIdx.x;                 // n*28 + t
    int n = b / kT, t = b - n * kT;
    const float* Pi = d_P + (size_t)(n * kSEQ + c_ti[t]) * kPC;
    const float* Pj = d_P + (size_t)(n * kSEQ + c_tj[t]) * kPC;
    int tid = threadIdx.x;
    float kv[5];
    float s = 0.f, ss = 0.f;
    #pragma unroll
    for (int u = 0; u < 5; u++) {
        int d = tid + (u << 8);
        if (d < kD) {
            float val = Pi[d] + Pj[kD + d] + kb[d];
            kv[u] = val; s += val; ss += val * val;
            d_qv[(size_t)b * kD + d] = Pi[2*kD + d] + Pj[3*kD + d] + vb[d];
        }
    }
    #pragma unroll
    for (int o = 16; o; o >>= 1) {
        s  += __shfl_xor_sync(0xffffffffu, s, o);
        ss += __shfl_xor_sync(0xffffffffu, ss, o);
    }
    __shared__ float shs[8], shss[8];
    __shared__ float sh_mu, sh_inv;
    if ((tid & 31) == 0) { shs[tid >> 5] = s; shss[tid >> 5] = ss; }
    __syncthreads();
    if (tid == 0) {
        float S = 0.f, SS = 0.f;
        #pragma unroll
        for (int w = 0; w < 8; w++) { S += shs[w]; SS += shss[w]; }
        float mu = S / (float)kD;
        sh_mu = mu;
        sh_inv = rsqrtf(SS / (float)kD - mu * mu + 1e-5f);
    }
    __syncthreads();
    float mu = sh_mu, inv = sh_inv;
    #pragma unroll
    for (int u = 0; u < 5; u++) {
        int d = tid + (u << 8);
        if (d < kD) d_qk[(size_t)b * kD + d] = (kv[u] - mu) * inv * g[d] + be[d];
    }
}

// ---------------- K3: per-class scores = Qk[14000,1152] @ Kc[140,1152]^T ----------------
__global__ __launch_bounds__(256) void k_scores() {
    const int c = blockIdx.z;
    const float* A = d_qk + (size_t)kNS * kT * kD;       // queries only
    const float* B = d_qk + (size_t)c * kKU * kD;        // class_k chunk
    float* C = d_attn + (size_t)c * kQR * kKUP;
    __shared__ __align__(16) float As[8][128];
    __shared__ __align__(16) float Bs[8][kKUP];
    const int tid = threadIdx.x;
    const int bm = blockIdx.x * 128;
    const int aRow = tid >> 1, aCol = (tid & 1) << 2;
    const int ty = tid >> 4, tx = tid & 15;              // 9 cols each
    const bool aOk = (bm + aRow) < kQR;
    u64 acc[4][9];
    #pragma unroll
    for (int u = 0; u < 4; u++)
        #pragma unroll
        for (int j = 0; j < 9; j++) acc[u][j] = 0ull;

    for (int k0 = 0; k0 < kD; k0 += 8) {
        float4 av = aOk ? *(const float4*)(A + (size_t)(bm + aRow) * kD + k0 + aCol)
                        : make_float4(0.f,0.f,0.f,0.f);
        As[aCol + 0][aRow] = av.x; As[aCol + 1][aRow] = av.y;
        As[aCol + 2][aRow] = av.z; As[aCol + 3][aRow] = av.w;
        for (int idx = tid; idx < kKUP * 8; idx += 256) {
            int nn = idx >> 3, kk = idx & 7;
            Bs[kk][nn] = (nn < kKU) ? B[(size_t)nn * kD + k0 + kk] : 0.f;
        }
        __syncthreads();
        #pragma unroll
        for (int kk = 0; kk < 8; kk++) {
            const u64* ap = (const u64*)&As[kk][ty << 3];
            u64 a2[4] = {ap[0], ap[1], ap[2], ap[3]};
            u64 b2[9];
            #pragma unroll
            for (int j = 0; j < 9; j++) { float bb = Bs[kk][tx * 9 + j]; b2[j] = pk2(bb, bb); }
            #pragma unroll
            for (int u = 0; u < 4; u++)
                #pragma unroll
                for (int j = 0; j < 9; j++) fma2(acc[u][j], a2[u], b2[j]);
        }
        __syncthreads();
    }
    const float sc = 1.0f / sqrtf((float)kD);
    #pragma unroll
    for (int u = 0; u < 4; u++) {
        int r0 = bm + (ty << 3) + 2 * u;
        #pragma unroll
        for (int j = 0; j < 9; j++) {
            float2 p = upk2(acc[u][j]);
            if (r0 < kQR)     C[(size_t)r0 * kKUP + tx * 9 + j]       = p.x * sc;
            if (r0 + 1 < kQR) C[(size_t)(r0 + 1) * kKUP + tx * 9 + j] = p.y * sc;
        }
    }
}

// ---------------- K4: softmax over 140 (one warp per row) ----------------
__global__ void k_softmax() {
    int row = (blockIdx.x << 3) + (threadIdx.x >> 5);
    int lane = threadIdx.x & 31;
    float* p = d_attn + (size_t)row * kKUP;
    float v[5];
    float m = -1e30f;
    #pragma unroll
    for (int u = 0; u < 5; u++) {
        int i = lane + (u << 5);
        v[u] = (i < kKU) ? p[i] : -1e30f;
        m = fmaxf(m, v[u]);
    }
    #pragma unroll
    for (int o = 16; o; o >>= 1) m = fmaxf(m, __shfl_xor_sync(0xffffffffu, m, o));
    float s = 0.f;
    #pragma unroll
    for (int u = 0; u < 5; u++) {
        float e = ((lane + (u << 5)) < kKU) ? expf(v[u] - m) : 0.f;
        v[u] = e; s += e;
    }
    #pragma unroll
    for (int o = 16; o; o >>= 1) s += __shfl_xor_sync(0xffffffffu, s, o);
    float inv = 1.0f / s;
    #pragma unroll
    for (int u = 0; u < 5; u++) {
        int i = lane + (u << 5);
        if (i < kKU) p[i] = v[u] * inv;
    }
}

// ---------------- K5: fused proto = attn @ Vc, dist, logits ----------------
// 576 threads, each owns 2 D-columns -> acc[14][2] u64 = 56 regs (no spills).
__global__ __launch_bounds__(576) void k_dist(const float* __restrict__ gt,
                                              const float* __restrict__ tw,
                                              float* __restrict__ out) {
    const int q = blockIdx.x, c = blockIdx.y;
    __shared__ __align__(16) float at[kKUP][kT];        // transposed attn tile (16128 B)
    __shared__ float red[18];
    const float* Ab = d_attn + ((size_t)c * kQR + (size_t)q * kT) * kKUP;
    const int tid = threadIdx.x;
    for (int idx = tid; idx < kT * kKUP; idx += 576) {
        int t = idx / kKUP, k = idx - t * kKUP;
        at[k][t] = Ab[idx];
    }
    __syncthreads();
    const float* Vc = d_qv + (size_t)c * kKU * kD;      // class_v: 140 x 1152
    const int d0 = tid << 1;                            // 576*2 = 1152 cols
    u64 acc[14][2];
    #pragma unroll
    for (int tp = 0; tp < 14; tp++) { acc[tp][0] = 0ull; acc[tp][1] = 0ull; }

    for (int k = 0; k < kKU; k++) {
        float2 v = *(const float2*)(Vc + (size_t)k * kD + d0);
        u64 vx = pk2(v.x, v.x), vy = pk2(v.y, v.y);
        const u64* ap = (const u64*)&at[k][0];          // 14 (t,t+1) pairs, broadcast
        #pragma unroll
        for (int tp = 0; tp < 14; tp++) {
            u64 a2 = ap[tp];
            fma2(acc[tp][0], a2, vx);
            fma2(acc[tp][1], a2, vy);
        }
    }
    const float* Qv = d_qv + (size_t)(kNS + q) * kT * kD + d0;
    float s = 0.f;
    #pragma unroll
    for (int tp = 0; tp < 14; tp++) {
        float2 qa = *(const float2*)(Qv + (size_t)(2 * tp) * kD);
        float2 qb = *(const float2*)(Qv + (size_t)(2 * tp + 1) * kD);
        float2 p0 = upk2(acc[tp][0]), p1 = upk2(acc[tp][1]);
        float dd;
        dd = qa.x - p0.x; s += dd * dd;  dd = qb.x - p0.y; s += dd * dd;
        dd = qa.y - p1.x; s += dd * dd;  dd = qb.y - p1.y; s += dd * dd;
    }
    #pragma unroll
    for (int o = 16; o; o >>= 1) s += __shfl_xor_sync(0xffffffffu, s, o);
    if ((tid & 31) == 0) red[tid >> 5] = s;
    __syncthreads();
    if (tid == 0) {
        float S = 0.f;
        #pragma unroll
        for (int w = 0; w < 18; w++) S += red[w];
        out[q * kWAY + c] = -(S / (float)kT) * gt[0] * tw[0];
    }
}

// ---------------- launch ----------------
extern "C" void kernel_launch(void* const* d_in, const int* in_sizes, int n_in,
                              void* d_out, int out_size) {
    const float* sup = (const float*)d_in[0];
    const float* qry = (const float*)d_in[2];
    const float* kw  = (const float*)d_in[3];
    const float* kb  = (const float*)d_in[4];
    const float* vw  = (const float*)d_in[5];
    const float* vb  = (const float*)d_in[6];
    const float* g   = (const float*)d_in[7];
    const float* be  = (const float*)d_in[8];
    const float* gt  = (const float*)d_in[9];
    const float* tw  = (const float*)d_in[10];
    float* out = (float*)d_out;

    k_build_x<<<kRX, 256>>>(sup, qry);
    k_build_w<<<kFEAT, 256>>>(kw, vw);
    k_gemm1<<<dim3(kPC / 128, (kRX + 127) / 128), 256>>>();
    k_combine<<<kNTR, 256>>>(kb, vb, g, be);
    k_scores<<<dim3((kQR + 127) / 128, 1, kWAY), 256>>>();
    k_softmax<<<(kWAY * kQR) / 8, 256>>>();
    k_dist<<<dim3(kNQ, kWAY), 576>>>(gt, tw, out);
}

// round 12
// speedup vs baseline: 10.5092x; 1.4314x over previous
#include <cuda_runtime.h>
#include <cuda_bf16.h>
#include <math.h>
#include <stdint.h>

// ---------------- problem constants ----------------
constexpr int kNS   = 25;
constexpr int kNQ   = 500;
constexpr int kNALL = kNS + kNQ;     // 525
constexpr int kSEQ  = 8;
constexpr int kFEAT = 2048;
constexpr int kD    = 1152;
constexpr int kT    = 28;
constexpr int kWAY  = 5;
constexpr int kKU   = 140;
constexpr int kKUP  = 144;
constexpr int kRX   = kNALL * kSEQ;  // 4200
constexpr int kPC   = 4 * kD;        // 4608
constexpr int kQR   = kNQ * kT;      // 14000
constexpr int kNTR  = kNALL * kT;    // 14700

// ---------------- scratch ----------------
__device__ __nv_bfloat16 d_Ah[(size_t)kRX * kFEAT];
__device__ __nv_bfloat16 d_Al[(size_t)kRX * kFEAT];
__device__ __nv_bfloat16 d_Bh[(size_t)kPC * kFEAT];   // [4608 n][2048 k]
__device__ __nv_bfloat16 d_Bl[(size_t)kPC * kFEAT];
__device__ float d_P[(size_t)kRX * kPC];
__device__ float d_qk[(size_t)kNTR * kD];
__device__ float d_qv[(size_t)kNTR * kD];
__device__ float d_attn[(size_t)kWAY * kQR * kKUP];

__constant__ int c_ti[kT] = {0,0,0,0,0,0,0,1,1,1,1,1,1,2,2,2,2,2,3,3,3,3,4,4,4,5,5,6};
__constant__ int c_tj[kT] = {1,2,3,4,5,6,7,2,3,4,5,6,7,3,4,5,6,7,4,5,6,7,5,6,7,6,7,7};

// ---------------- f32x2 helpers ----------------
typedef unsigned long long u64;
__device__ __forceinline__ u64 pk2(float lo, float hi) {
    u64 r; asm("mov.b64 %0,{%1,%2};" : "=l"(r) : "f"(lo), "f"(hi)); return r;
}
__device__ __forceinline__ void fma2(u64& d, u64 a, u64 b) {
    asm("fma.rn.f32x2 %0,%1,%2,%0;" : "+l"(d) : "l"(a), "l"(b));
}
__device__ __forceinline__ float2 upk2(u64 v) {
    float2 f; asm("mov.b64 {%0,%1},%2;" : "=f"(f.x), "=f"(f.y) : "l"(v)); return f;
}

// ---------------- smem / hmma helpers ----------------
__device__ __forceinline__ uint32_t smem_u32(const void* p) {
    uint32_t a;
    asm("{ .reg .u64 t; cvta.to.shared.u64 t, %1; cvt.u32.u64 %0, t; }" : "=r"(a) : "l"(p));
    return a;
}
__device__ __forceinline__ uint32_t swz(uint32_t o) { return o ^ ((o >> 3) & 0x70); }
__device__ __forceinline__ void st128s(uint32_t a, uint4 v) {
    asm volatile("st.shared.v4.b32 [%0],{%1,%2,%3,%4};" :: "r"(a), "r"(v.x), "r"(v.y), "r"(v.z), "r"(v.w) : "memory");
}
__device__ __forceinline__ void ldsm_x4(uint32_t* r, uint32_t addr) {
    asm volatile("ldmatrix.sync.aligned.m8n8.x4.shared.b16 {%0,%1,%2,%3}, [%4];"
                 : "=r"(r[0]), "=r"(r[1]), "=r"(r[2]), "=r"(r[3]) : "r"(addr));
}
__device__ __forceinline__ void mma16816(float* d, const uint32_t* a, const uint32_t* b) {
    asm volatile(
        "mma.sync.aligned.m16n8k16.row.col.f32.bf16.bf16.f32 "
        "{%0,%1,%2,%3}, {%4,%5,%6,%7}, {%8,%9}, {%0,%1,%2,%3};"
        : "+f"(d[0]), "+f"(d[1]), "+f"(d[2]), "+f"(d[3])
        : "r"(a[0]), "r"(a[1]), "r"(a[2]), "r"(a[3]), "r"(b[0]), "r"(b[1]));
}

// ---------------- K0a: PE add + hi/lo bf16 split of frames ----------------
__global__ void k_build_ax(const float* __restrict__ sup, const float* __restrict__ qry) {
    int r = blockIdx.x;                 // 0..4199
    int n = r >> 3, f = r & 7;
    const float* src = (n < kNS) ? (sup + (size_t)r * kFEAT)
                                 : (qry + (size_t)(r - kNS * kSEQ) * kFEAT);
    const float cc = -logf(10000.0f) / (float)kFEAT;
    float pf = (float)f;
    for (int d = threadIdx.x; d < kFEAT; d += blockDim.x) {
        int j2 = d & ~1;
        float v  = pf * expf(cc * (float)j2);
        float pe = (d & 1) ? cosf(v) : sinf(v);
        float x = src[d] + pe;
        __nv_bfloat16 h = __float2bfloat16(x);
        d_Ah[(size_t)r * kFEAT + d] = h;
        d_Al[(size_t)r * kFEAT + d] = __float2bfloat16(x - __bfloat162float(h));
    }
}

// ---------------- K0b: transpose + hi/lo split of weights -> B[n][k] ----------------
__global__ void k_split_b(const float* __restrict__ kw, const float* __restrict__ vw) {
    __shared__ float tile[32][33];
    int kb = blockIdx.x * 32, nb = blockIdx.y * 32;
    int tx = threadIdx.x, ty = threadIdx.y;     // (32,8)
    int sel = nb / kD;                           // 1152 % 32 == 0 -> tile within one sel
    const float* src = (sel < 2) ? kw : vw;
    int krow = kb + (sel & 1) * kFEAT;
    int col0 = nb % kD;
    #pragma unroll
    for (int i = 0; i < 4; i++)
        tile[ty + 8*i][tx] = src[(size_t)(krow + ty + 8*i) * kD + col0 + tx];
    __syncthreads();
    #pragma unroll
    for (int i = 0; i < 4; i++) {
        float x = tile[tx][ty + 8*i];
        __nv_bfloat16 h = __float2bfloat16(x);
        size_t o = (size_t)(nb + ty + 8*i) * kFEAT + kb + tx;
        d_Bh[o] = h;
        d_Bl[o] = __float2bfloat16(x - __bfloat162float(h));
    }
}

// ---------------- K1: split-bf16 HMMA GEMM  P = X @ Wcat ----------------
// CTA tile 128x128, 8 warps as 2(M)x4(N), warp tile 64x32.
// 3 passes per k-chunk: Ah*Bh + Ah*Bl + Al*Bh, fp32 accumulators.
constexpr int kKC = 64;               // k elems per chunk (128B rows)
__global__ __launch_bounds__(256) void k1_hmma() {
    extern __shared__ __align__(16) char dsm[];
    const uint32_t sb = smem_u32(dsm);
    const uint32_t sAh = sb, sAl = sb + 16384, sBh = sb + 32768, sBl = sb + 49152;
    const int tid  = threadIdx.x;
    const int wid  = tid >> 5, lane = tid & 31;
    const int wm   = wid >> 2, wn = wid & 3;    // warp grid 2x4
    const int bm   = blockIdx.y * 128;
    const int bn   = blockIdx.x * 128;

    float acc[4][4][4];
    #pragma unroll
    for (int mi = 0; mi < 4; mi++)
        #pragma unroll
        for (int ni = 0; ni < 4; ni++)
            #pragma unroll
            for (int e = 0; e < 4; e++) acc[mi][ni][e] = 0.f;

    // precomputed ldmatrix smem offsets (within a tile) for this lane
    const int aRowL = (lane & 15);              // + mtile*16
    const int aKoffL = (lane >> 4) << 3;        // 0 or 8
    const int bGrp  = lane >> 3;                // 0..3
    const int bRowL = ((bGrp >> 1) << 3) + (lane & 7);   // + ntile16*16
    const int bKoffL = (bGrp & 1) << 3;

    for (int kc = 0; kc < kFEAT; kc += kKC) {
        // ---- stage 4 tiles (A:128x64, B:128x64, hi+lo) ----
        #pragma unroll
        for (int j = 0; j < 4; j++) {
            int u = tid + j * 256;              // 1024 16B-units per tile
            int row = u >> 3, bc = (u & 7) << 4;
            int gr = bm + row;
            size_t goA = (size_t)gr * kFEAT + kc + (bc >> 1);
            uint4 vh = make_uint4(0u,0u,0u,0u), vl = make_uint4(0u,0u,0u,0u);
            if (gr < kRX) { vh = *(const uint4*)(d_Ah + goA); vl = *(const uint4*)(d_Al + goA); }
            uint32_t so = swz(row * 128 + bc);
            st128s(sAh + so, vh);
            st128s(sAl + so, vl);
        }
        #pragma unroll
        for (int j = 0; j < 4; j++) {
            int u = tid + j * 256;
            int row = u >> 3, bc = (u & 7) << 4;
            size_t goB = (size_t)(bn + row) * kFEAT + kc + (bc >> 1);
            uint32_t so = swz(row * 128 + bc);
            st128s(sBh + so, *(const uint4*)(d_Bh + goB));
            st128s(sBl + so, *(const uint4*)(d_Bl + goB));
        }
        __syncthreads();

        // ---- compute: 3 split passes over this chunk ----
        #pragma unroll
        for (int pass = 0; pass < 3; pass++) {
            const uint32_t Ab = (pass == 2) ? sAl : sAh;
            const uint32_t Bb = (pass == 1) ? sBl : sBh;
            #pragma unroll
            for (int kt = 0; kt < kKC / 16; kt++) {
                uint32_t a[4][4];
                #pragma unroll
                for (int mi = 0; mi < 4; mi++) {
                    int row = wm * 64 + mi * 16 + aRowL;
                    int kcol = kt * 16 + aKoffL;
                    ldsm_x4(a[mi], Ab + swz(row * 128 + kcol * 2));
                }
                uint32_t b[4][2];
                #pragma unroll
                for (int bi = 0; bi < 2; bi++) {
                    int row = wn * 32 + bi * 16 + bRowL;
                    int kcol = kt * 16 + bKoffL;
                    uint32_t r[4];
                    ldsm_x4(r, Bb + swz(row * 128 + kcol * 2));
                    b[2*bi][0] = r[0]; b[2*bi][1] = r[1];
                    b[2*bi+1][0] = r[2]; b[2*bi+1][1] = r[3];
                }
                #pragma unroll
                for (int mi = 0; mi < 4; mi++)
                    #pragma unroll
                    for (int ni = 0; ni < 4; ni++)
                        mma16816(acc[mi][ni], a[mi], b[ni]);
            }
        }
        __syncthreads();
    }

    // ---- epilogue: c0,c1 -> (row, col..col+1); c2,c3 -> (row+8, ...) ----
    const int colB = bn + wn * 32 + (lane & 3) * 2;
    #pragma unroll
    for (int mi = 0; mi < 4; mi++) {
        int row0 = bm + wm * 64 + mi * 16 + (lane >> 2);
        #pragma unroll
        for (int ni = 0; ni < 4; ni++) {
            int col = colB + ni * 8;
            if (row0 < kRX)
                *(float2*)(d_P + (size_t)row0 * kPC + col) = make_float2(acc[mi][ni][0], acc[mi][ni][1]);
            if (row0 + 8 < kRX)
                *(float2*)(d_P + (size_t)(row0 + 8) * kPC + col) = make_float2(acc[mi][ni][2], acc[mi][ni][3]);
        }
    }
}

// ---------------- K2: tuple combine + bias + LayerNorm(K) ----------------
__global__ __launch_bounds__(256) void k_combine(const float* __restrict__ kb,
                                                 const float* __restrict__ vb,
                                                 const float* __restrict__ g,
                                                 const float* __restrict__ be) {
    int b = blockIdx.x;
    int n = b / kT, t = b - n * kT;
    const float* Pi = d_P + (size_t)(n * kSEQ + c_ti[t]) * kPC;
    const float* Pj = d_P + (size_t)(n * kSEQ + c_tj[t]) * kPC;
    int tid = threadIdx.x;
    float kv[5];
    float s = 0.f, ss = 0.f;
    #pragma unroll
    for (int u = 0; u < 5; u++) {
        int d = tid + (u << 8);
        if (d < kD) {
            float val = Pi[d] + Pj[kD + d] + kb[d];
            kv[u] = val; s += val; ss += val * val;
            d_qv[(size_t)b * kD + d] = Pi[2*kD + d] + Pj[3*kD + d] + vb[d];
        }
    }
    #pragma unroll
    for (int o = 16; o; o >>= 1) {
        s  += __shfl_xor_sync(0xffffffffu, s, o);
        ss += __shfl_xor_sync(0xffffffffu, ss, o);
    }
    __shared__ float shs[8], shss[8];
    __shared__ float sh_mu, sh_inv;
    if ((tid & 31) == 0) { shs[tid >> 5] = s; shss[tid >> 5] = ss; }
    __syncthreads();
    if (tid == 0) {
        float S = 0.f, SS = 0.f;
        #pragma unroll
        for (int w = 0; w < 8; w++) { S += shs[w]; SS += shss[w]; }
        float mu = S / (float)kD;
        sh_mu = mu;
        sh_inv = rsqrtf(SS / (float)kD - mu * mu + 1e-5f);
    }
    __syncthreads();
    float mu = sh_mu, inv = sh_inv;
    #pragma unroll
    for (int u = 0; u < 5; u++) {
        int d = tid + (u << 8);
        if (d < kD) d_qk[(size_t)b * kD + d] = (kv[u] - mu) * inv * g[d] + be[d];
    }
}

// ---------------- K3: per-class scores ----------------
__global__ __launch_bounds__(256) void k_scores() {
    const int c = blockIdx.z;
    const float* A = d_qk + (size_t)kNS * kT * kD;
    const float* B = d_qk + (size_t)c * kKU * kD;
    float* C = d_attn + (size_t)c * kQR * kKUP;
    __shared__ __align__(16) float As[8][128];
    __shared__ __align__(16) float Bs[8][kKUP];
    const int tid = threadIdx.x;
    const int bm = blockIdx.x * 128;
    const int aRow = tid >> 1, aCol = (tid & 1) << 2;
    const int ty = tid >> 4, tx = tid & 15;
    const bool aOk = (bm + aRow) < kQR;
    u64 acc[4][9];
    #pragma unroll
    for (int u = 0; u < 4; u++)
        #pragma unroll
        for (int j = 0; j < 9; j++) acc[u][j] = 0ull;

    for (int k0 = 0; k0 < kD; k0 += 8) {
        float4 av = aOk ? *(const float4*)(A + (size_t)(bm + aRow) * kD + k0 + aCol)
                        : make_float4(0.f,0.f,0.f,0.f);
        As[aCol + 0][aRow] = av.x; As[aCol + 1][aRow] = av.y;
        As[aCol + 2][aRow] = av.z; As[aCol + 3][aRow] = av.w;
        for (int idx = tid; idx < kKUP * 8; idx += 256) {
            int nn = idx >> 3, kk = idx & 7;
            Bs[kk][nn] = (nn < kKU) ? B[(size_t)nn * kD + k0 + kk] : 0.f;
        }
        __syncthreads();
        #pragma unroll
        for (int kk = 0; kk < 8; kk++) {
            const u64* ap = (const u64*)&As[kk][ty << 3];
            u64 a2[4] = {ap[0], ap[1], ap[2], ap[3]};
            u64 b2[9];
            #pragma unroll
            for (int j = 0; j < 9; j++) { float bb = Bs[kk][tx * 9 + j]; b2[j] = pk2(bb, bb); }
            #pragma unroll
            for (int u = 0; u < 4; u++)
                #pragma unroll
                for (int j = 0; j < 9; j++) fma2(acc[u][j], a2[u], b2[j]);
        }
        __syncthreads();
    }
    const float sc = 1.0f / sqrtf((float)kD);
    #pragma unroll
    for (int u = 0; u < 4; u++) {
        int r0 = bm + (ty << 3) + 2 * u;
        #pragma unroll
        for (int j = 0; j < 9; j++) {
            float2 p = upk2(acc[u][j]);
            if (r0 < kQR)     C[(size_t)r0 * kKUP + tx * 9 + j]       = p.x * sc;
            if (r0 + 1 < kQR) C[(size_t)(r0 + 1) * kKUP + tx * 9 + j] = p.y * sc;
        }
    }
}

// ---------------- K4: softmax ----------------
__global__ void k_softmax() {
    int row = (blockIdx.x << 3) + (threadIdx.x >> 5);
    int lane = threadIdx.x & 31;
    float* p = d_attn + (size_t)row * kKUP;
    float v[5];
    float m = -1e30f;
    #pragma unroll
    for (int u = 0; u < 5; u++) {
        int i = lane + (u << 5);
        v[u] = (i < kKU) ? p[i] : -1e30f;
        m = fmaxf(m, v[u]);
    }
    #pragma unroll
    for (int o = 16; o; o >>= 1) m = fmaxf(m, __shfl_xor_sync(0xffffffffu, m, o));
    float s = 0.f;
    #pragma unroll
    for (int u = 0; u < 5; u++) {
        float e = ((lane + (u << 5)) < kKU) ? expf(v[u] - m) : 0.f;
        v[u] = e; s += e;
    }
    #pragma unroll
    for (int o = 16; o; o >>= 1) s += __shfl_xor_sync(0xffffffffu, s, o);
    float inv = 1.0f / s;
    #pragma unroll
    for (int u = 0; u < 5; u++) {
        int i = lane + (u << 5);
        if (i < kKU) p[i] = v[u] * inv;
    }
}

// ---------------- K5: fused proto/dist/logits ----------------
__global__ __launch_bounds__(576) void k_dist(const float* __restrict__ gt,
                                              const float* __restrict__ tw,
                                              float* __restrict__ out) {
    const int q = blockIdx.x, c = blockIdx.y;
    __shared__ __align__(16) float at[kKUP][kT];
    __shared__ float red[18];
    const float* Ab = d_attn + ((size_t)c * kQR + (size_t)q * kT) * kKUP;
    const int tid = threadIdx.x;
    for (int idx = tid; idx < kT * kKUP; idx += 576) {
        int t = idx / kKUP, k = idx - t * kKUP;
        at[k][t] = Ab[idx];
    }
    __syncthreads();
    const float* Vc = d_qv + (size_t)c * kKU * kD;
    const int d0 = tid << 1;
    u64 acc[14][2];
    #pragma unroll
    for (int tp = 0; tp < 14; tp++) { acc[tp][0] = 0ull; acc[tp][1] = 0ull; }

    for (int k = 0; k < kKU; k++) {
        float2 v = *(const float2*)(Vc + (size_t)k * kD + d0);
        u64 vx = pk2(v.x, v.x), vy = pk2(v.y, v.y);
        const u64* ap = (const u64*)&at[k][0];
        #pragma unroll
        for (int tp = 0; tp < 14; tp++) {
            u64 a2 = ap[tp];
            fma2(acc[tp][0], a2, vx);
            fma2(acc[tp][1], a2, vy);
        }
    }
    const float* Qv = d_qv + (size_t)(kNS + q) * kT * kD + d0;
    float s = 0.f;
    #pragma unroll
    for (int tp = 0; tp < 14; tp++) {
        float2 qa = *(const float2*)(Qv + (size_t)(2 * tp) * kD);
        float2 qb = *(const float2*)(Qv + (size_t)(2 * tp + 1) * kD);
        float2 p0 = upk2(acc[tp][0]), p1 = upk2(acc[tp][1]);
        float dd;
        dd = qa.x - p0.x; s += dd * dd;  dd = qb.x - p0.y; s += dd * dd;
        dd = qa.y - p1.x; s += dd * dd;  dd = qb.y - p1.y; s += dd * dd;
    }
    #pragma unroll
    for (int o = 16; o; o >>= 1) s += __shfl_xor_sync(0xffffffffu, s, o);
    if ((tid & 31) == 0) red[tid >> 5] = s;
    __syncthreads();
    if (tid == 0) {
        float S = 0.f;
        #pragma unroll
        for (int w = 0; w < 18; w++) S += red[w];
        out[q * kWAY + c] = -(S / (float)kT) * gt[0] * tw[0];
    }
}

// ---------------- launch ----------------
extern "C" void kernel_launch(void* const* d_in, const int* in_sizes, int n_in,
                              void* d_out, int out_size) {
    const float* sup = (const float*)d_in[0];
    const float* qry = (const float*)d_in[2];
    const float* kw  = (const float*)d_in[3];
    const float* kb  = (const float*)d_in[4];
    const float* vw  = (const float*)d_in[5];
    const float* vb  = (const float*)d_in[6];
    const float* g   = (const float*)d_in[7];
    const float* be  = (const float*)d_in[8];
    const float* gt  = (const float*)d_in[9];
    const float* tw  = (const float*)d_in[10];
    float* out = (float*)d_out;

    cudaFuncSetAttribute(k1_hmma, cudaFuncAttributeMaxDynamicSharedMemorySize, 65536);

    k_build_ax<<<kRX, 256>>>(sup, qry);
    k_split_b<<<dim3(kFEAT / 32, kPC / 32), dim3(32, 8)>>>(kw, vw);
    k1_hmma<<<dim3(kPC / 128, (kRX + 127) / 128), 256, 65536>>>();
    k_combine<<<kNTR, 256>>>(kb, vb, g, be);
    k_scores<<<dim3((kQR + 127) / 128, 1, kWAY), 256>>>();
    k_softmax<<<(kWAY * kQR) / 8, 256>>>();
    k_dist<<<dim3(kNQ, kWAY), 576>>>(gt, tw, out);
}

// round 14
// speedup vs baseline: 13.6777x; 1.3015x over previous
#include <cuda_runtime.h>
#include <cuda_bf16.h>
#include <math.h>
#include <stdint.h>

// ---------------- problem constants ----------------
constexpr int kNS   = 25;
constexpr int kNQ   = 500;
constexpr int kNALL = kNS + kNQ;     // 525
constexpr int kSEQ  = 8;
constexpr int kFEAT = 2048;
constexpr int kD    = 1152;
constexpr int kT    = 28;
constexpr int kWAY  = 5;
constexpr int kKU   = 140;
constexpr int kKUP  = 144;
constexpr int kRX   = kNALL * kSEQ;  // 4200
constexpr int kPC   = 4 * kD;        // 4608
constexpr int kQR   = kNQ * kT;      // 14000
constexpr int kNTR  = kNALL * kT;    // 14700

// ---------------- scratch ----------------
__device__ __nv_bfloat16 d_Ah[(size_t)kRX * kFEAT];
__device__ __nv_bfloat16 d_Al[(size_t)kRX * kFEAT];
__device__ __nv_bfloat16 d_Bh[(size_t)kPC * kFEAT];   // [4608 n][2048 k]
__device__ __nv_bfloat16 d_Bl[(size_t)kPC * kFEAT];
__device__ float d_P[(size_t)kRX * kPC];
__device__ __nv_bfloat16 d_Kh[(size_t)kNTR * kD];     // LN'd K, hi/lo
__device__ __nv_bfloat16 d_Kl[(size_t)kNTR * kD];
__device__ float d_qv[(size_t)kNTR * kD];             // V features fp32
__device__ float d_attn[(size_t)kWAY * kQR * kKUP];   // scores (fp32)
__device__ __nv_bfloat16 d_ATh[(size_t)kWAY * kQR * kKUP];  // attn hi/lo
__device__ __nv_bfloat16 d_ATl[(size_t)kWAY * kQR * kKUP];
__device__ __nv_bfloat16 d_VTh[(size_t)kWAY * kD * kKUP];   // support V^T hi/lo
__device__ __nv_bfloat16 d_VTl[(size_t)kWAY * kD * kKUP];
__device__ float d_distq[kWAY * kNQ];

__constant__ int c_ti[kT] = {0,0,0,0,0,0,0,1,1,1,1,1,1,2,2,2,2,2,3,3,3,3,4,4,4,5,5,6};
__constant__ int c_tj[kT] = {1,2,3,4,5,6,7,2,3,4,5,6,7,3,4,5,6,7,4,5,6,7,5,6,7,6,7,7};

// ---------------- smem / hmma helpers ----------------
__device__ __forceinline__ uint32_t smem_u32(const void* p) {
    uint32_t a;
    asm("{ .reg .u64 t; cvta.to.shared.u64 t, %1; cvt.u32.u64 %0, t; }" : "=r"(a) : "l"(p));
    return a;
}
__device__ __forceinline__ uint32_t swz(uint32_t o) { return o ^ ((o >> 3) & 0x70); }
__device__ __forceinline__ void st128s(uint32_t a, uint4 v) {
    asm volatile("st.shared.v4.b32 [%0],{%1,%2,%3,%4};" :: "r"(a), "r"(v.x), "r"(v.y), "r"(v.z), "r"(v.w) : "memory");
}
__device__ __forceinline__ void ldsm_x4(uint32_t* r, uint32_t addr) {
    asm volatile("ldmatrix.sync.aligned.m8n8.x4.shared.b16 {%0,%1,%2,%3}, [%4];"
                 : "=r"(r[0]), "=r"(r[1]), "=r"(r[2]), "=r"(r[3]) : "r"(addr));
}
__device__ __forceinline__ void mma16816(float* d, const uint32_t* a, const uint32_t* b) {
    asm volatile(
        "mma.sync.aligned.m16n8k16.row.col.f32.bf16.bf16.f32 "
        "{%0,%1,%2,%3}, {%4,%5,%6,%7}, {%8,%9}, {%0,%1,%2,%3};"
        : "+f"(d[0]), "+f"(d[1]), "+f"(d[2]), "+f"(d[3])
        : "r"(a[0]), "r"(a[1]), "r"(a[2]), "r"(a[3]), "r"(b[0]), "r"(b[1]));
}

// ---------------- K0a: PE add + hi/lo bf16 split of frames ----------------
__global__ void k_build_ax(const float* __restrict__ sup, const float* __restrict__ qry) {
    int r = blockIdx.x;                 // 0..4199
    int n = r >> 3, f = r & 7;
    const float* src = (n < kNS) ? (sup + (size_t)r * kFEAT)
                                 : (qry + (size_t)(r - kNS * kSEQ) * kFEAT);
    const float cc = -logf(10000.0f) / (float)kFEAT;
    float pf = (float)f;
    for (int d = threadIdx.x; d < kFEAT; d += blockDim.x) {
        int j2 = d & ~1;
        float v  = pf * expf(cc * (float)j2);
        float pe = (d & 1) ? cosf(v) : sinf(v);
        float x = src[d] + pe;
        __nv_bfloat16 h = __float2bfloat16(x);
        d_Ah[(size_t)r * kFEAT + d] = h;
        d_Al[(size_t)r * kFEAT + d] = __float2bfloat16(x - __bfloat162float(h));
    }
}

// ---------------- K0b: transpose + hi/lo split of weights -> B[n][k] ----------------
__global__ void k_split_b(const float* __restrict__ kw, const float* __restrict__ vw) {
    __shared__ float tile[32][33];
    int kb = blockIdx.x * 32, nb = blockIdx.y * 32;
    int tx = threadIdx.x, ty = threadIdx.y;     // (32,8)
    int sel = nb / kD;
    const float* src = (sel < 2) ? kw : vw;
    int krow = kb + (sel & 1) * kFEAT;
    int col0 = nb % kD;
    #pragma unroll
    for (int i = 0; i < 4; i++)
        tile[ty + 8*i][tx] = src[(size_t)(krow + ty + 8*i) * kD + col0 + tx];
    __syncthreads();
    #pragma unroll
    for (int i = 0; i < 4; i++) {
        float x = tile[tx][ty + 8*i];
        __nv_bfloat16 h = __float2bfloat16(x);
        size_t o = (size_t)(nb + ty + 8*i) * kFEAT + kb + tx;
        d_Bh[o] = h;
        d_Bl[o] = __float2bfloat16(x - __bfloat162float(h));
    }
}

// ---------------- K1: split-bf16 HMMA GEMM  P = X @ Wcat (unchanged, validated) ----------------
constexpr int kKC = 64;
__global__ __launch_bounds__(256) void k1_hmma() {
    extern __shared__ __align__(16) char dsm[];
    const uint32_t sb = smem_u32(dsm);
    const uint32_t sAh = sb, sAl = sb + 16384, sBh = sb + 32768, sBl = sb + 49152;
    const int tid  = threadIdx.x;
    const int wid  = tid >> 5, lane = tid & 31;
    const int wm   = wid >> 2, wn = wid & 3;
    const int bm   = blockIdx.y * 128;
    const int bn   = blockIdx.x * 128;

    float acc[4][4][4];
    #pragma unroll
    for (int mi = 0; mi < 4; mi++)
        #pragma unroll
        for (int ni = 0; ni < 4; ni++)
            #pragma unroll
            for (int e = 0; e < 4; e++) acc[mi][ni][e] = 0.f;

    const int aRowL = (lane & 15);
    const int aKoffL = (lane >> 4) << 3;
    const int bGrp  = lane >> 3;
    const int bRowL = ((bGrp >> 1) << 3) + (lane & 7);
    const int bKoffL = (bGrp & 1) << 3;

    for (int kc = 0; kc < kFEAT; kc += kKC) {
        #pragma unroll
        for (int j = 0; j < 4; j++) {
            int u = tid + j * 256;
            int row = u >> 3, bc = (u & 7) << 4;
            int gr = bm + row;
            size_t goA = (size_t)gr * kFEAT + kc + (bc >> 1);
            uint4 vh = make_uint4(0u,0u,0u,0u), vl = make_uint4(0u,0u,0u,0u);
            if (gr < kRX) { vh = *(const uint4*)(d_Ah + goA); vl = *(const uint4*)(d_Al + goA); }
            uint32_t so = swz(row * 128 + bc);
            st128s(sAh + so, vh);
            st128s(sAl + so, vl);
        }
        #pragma unroll
        for (int j = 0; j < 4; j++) {
            int u = tid + j * 256;
            int row = u >> 3, bc = (u & 7) << 4;
            size_t goB = (size_t)(bn + row) * kFEAT + kc + (bc >> 1);
            uint32_t so = swz(row * 128 + bc);
            st128s(sBh + so, *(const uint4*)(d_Bh + goB));
            st128s(sBl + so, *(const uint4*)(d_Bl + goB));
        }
        __syncthreads();
        #pragma unroll
        for (int pass = 0; pass < 3; pass++) {
            const uint32_t Ab = (pass == 2) ? sAl : sAh;
            const uint32_t Bb = (pass == 1) ? sBl : sBh;
            #pragma unroll
            for (int kt = 0; kt < kKC / 16; kt++) {
                uint32_t a[4][4];
                #pragma unroll
                for (int mi = 0; mi < 4; mi++) {
                    int row = wm * 64 + mi * 16 + aRowL;
                    int kcol = kt * 16 + aKoffL;
                    ldsm_x4(a[mi], Ab + swz(row * 128 + kcol * 2));
                }
                uint32_t b[4][2];
                #pragma unroll
                for (int bi = 0; bi < 2; bi++) {
                    int row = wn * 32 + bi * 16 + bRowL;
                    int kcol = kt * 16 + bKoffL;
                    uint32_t r[4];
                    ldsm_x4(r, Bb + swz(row * 128 + kcol * 2));
                    b[2*bi][0] = r[0]; b[2*bi][1] = r[1];
                    b[2*bi+1][0] = r[2]; b[2*bi+1][1] = r[3];
                }
                #pragma unroll
                for (int mi = 0; mi < 4; mi++)
                    #pragma unroll
                    for (int ni = 0; ni < 4; ni++)
                        mma16816(acc[mi][ni], a[mi], b[ni]);
            }
        }
        __syncthreads();
    }
    const int colB = bn + wn * 32 + (lane & 3) * 2;
    #pragma unroll
    for (int mi = 0; mi < 4; mi++) {
        int row0 = bm + wm * 64 + mi * 16 + (lane >> 2);
        #pragma unroll
        for (int ni = 0; ni < 4; ni++) {
            int col = colB + ni * 8;
            if (row0 < kRX)
                *(float2*)(d_P + (size_t)row0 * kPC + col) = make_float2(acc[mi][ni][0], acc[mi][ni][1]);
            if (row0 + 8 < kRX)
                *(float2*)(d_P + (size_t)(row0 + 8) * kPC + col) = make_float2(acc[mi][ni][2], acc[mi][ni][3]);
        }
    }
}

// ---------------- K2: tuple combine + bias + LN(K) -> split bf16 K; fp32 V ----------------
__global__ __launch_bounds__(256) void k_combine(const float* __restrict__ kb,
                                                 const float* __restrict__ vb,
                                                 const float* __restrict__ g,
                                                 const float* __restrict__ be) {
    int b = blockIdx.x;
    int n = b / kT, t = b - n * kT;
    const float* Pi = d_P + (size_t)(n * kSEQ + c_ti[t]) * kPC;
    const float* Pj = d_P + (size_t)(n * kSEQ + c_tj[t]) * kPC;
    int tid = threadIdx.x;
    float kv[5];
    float s = 0.f, ss = 0.f;
    #pragma unroll
    for (int u = 0; u < 5; u++) {
        int d = tid + (u << 8);
        if (d < kD) {
            float val = Pi[d] + Pj[kD + d] + kb[d];
            kv[u] = val; s += val; ss += val * val;
            d_qv[(size_t)b * kD + d] = Pi[2*kD + d] + Pj[3*kD + d] + vb[d];
        }
    }
    #pragma unroll
    for (int o = 16; o; o >>= 1) {
        s  += __shfl_xor_sync(0xffffffffu, s, o);
        ss += __shfl_xor_sync(0xffffffffu, ss, o);
    }
    __shared__ float shs[8], shss[8];
    __shared__ float sh_mu, sh_inv;
    if ((tid & 31) == 0) { shs[tid >> 5] = s; shss[tid >> 5] = ss; }
    __syncthreads();
    if (tid == 0) {
        float S = 0.f, SS = 0.f;
        #pragma unroll
        for (int w = 0; w < 8; w++) { S += shs[w]; SS += shss[w]; }
        float mu = S / (float)kD;
        sh_mu = mu;
        sh_inv = rsqrtf(SS / (float)kD - mu * mu + 1e-5f);
    }
    __syncthreads();
    float mu = sh_mu, inv = sh_inv;
    #pragma unroll
    for (int u = 0; u < 5; u++) {
        int d = tid + (u << 8);
        if (d < kD) {
            float kn = (kv[u] - mu) * inv * g[d] + be[d];
            __nv_bfloat16 h = __float2bfloat16(kn);
            d_Kh[(size_t)b * kD + d] = h;
            d_Kl[(size_t)b * kD + d] = __float2bfloat16(kn - __bfloat162float(h));
        }
    }
}

// ---------------- K2b: transpose support V -> VT[c][d][u] hi/lo bf16 ----------------
__global__ void k_vt(int dummy) {
    __shared__ float t[32][33];
    int u0 = blockIdx.x * 32, d0 = blockIdx.y * 32, c = blockIdx.z;
    int tx = threadIdx.x, ty = threadIdx.y;     // (32,8)
    #pragma unroll
    for (int i = 0; i < 4; i++) {
        int u = u0 + ty + 8*i;
        t[ty + 8*i][tx] = (u < kKU) ? d_qv[((size_t)c * kKU + u) * kD + d0 + tx] : 0.f;
    }
    __syncthreads();
    #pragma unroll
    for (int i = 0; i < 4; i++) {
        int d = d0 + ty + 8*i;
        int u = u0 + tx;
        if (u < kKUP) {
            float x = t[tx][ty + 8*i];
            __nv_bfloat16 h = __float2bfloat16(x);
            size_t o = ((size_t)c * kD + d) * kKUP + u;
            d_VTh[o] = h;
            d_VTl[o] = __float2bfloat16(x - __bfloat162float(h));
        }
    }
}

// ---------------- K3: scores via split-bf16 HMMA ----------------
// CTA 128(M q-rows) x 160(N padded support-tuples), K=1152 in 64-chunks.
// 8 warps 4(M)x2(N): warp tile 32x80.
__global__ __launch_bounds__(256) void k_scores_mma() {
    extern __shared__ __align__(16) char dsm[];
    const uint32_t sb = smem_u32(dsm);
    const uint32_t sAh = sb, sAl = sb + 16384;
    const uint32_t sBh = sb + 32768, sBl = sb + 32768 + 20480;
    const int tid = threadIdx.x;
    const int wid = tid >> 5, lane = tid & 31;
    const int wm = wid >> 1, wn = wid & 1;
    const int c  = blockIdx.z;
    const int bm = blockIdx.x * 128;

    float acc[2][10][4];
    #pragma unroll
    for (int mi = 0; mi < 2; mi++)
        #pragma unroll
        for (int ni = 0; ni < 10; ni++)
            #pragma unroll
            for (int e = 0; e < 4; e++) acc[mi][ni][e] = 0.f;

    const int aRowL = (lane & 15);
    const int aKoffL = (lane >> 4) << 3;
    const int bGrp  = lane >> 3;
    const int bRowL = ((bGrp >> 1) << 3) + (lane & 7);
    const int bKoffL = (bGrp & 1) << 3;

    for (int kc = 0; kc < kD; kc += kKC) {
        #pragma unroll
        for (int j = 0; j < 4; j++) {               // A: 128x64 hi/lo
            int u = tid + j * 256;
            int row = u >> 3, bc = (u & 7) << 4;
            uint4 vh = make_uint4(0u,0u,0u,0u), vl = make_uint4(0u,0u,0u,0u);
            if (bm + row < kQR) {
                size_t go = (size_t)(kNS * kT + bm + row) * kD + kc + (bc >> 1);
                vh = *(const uint4*)(d_Kh + go); vl = *(const uint4*)(d_Kl + go);
            }
            uint32_t so = swz(row * 128 + bc);
            st128s(sAh + so, vh);
            st128s(sAl + so, vl);
        }
        #pragma unroll
        for (int j = 0; j < 5; j++) {               // B: 160x64 hi/lo
            int u = tid + j * 256;
            int row = u >> 3, bc = (u & 7) << 4;
            uint4 vh = make_uint4(0u,0u,0u,0u), vl = make_uint4(0u,0u,0u,0u);
            if (row < kKU) {
                size_t go = (size_t)(c * kKU + row) * kD + kc + (bc >> 1);
                vh = *(const uint4*)(d_Kh + go); vl = *(const uint4*)(d_Kl + go);
            }
            uint32_t so = swz(row * 128 + bc);
            st128s(sBh + so, vh);
            st128s(sBl + so, vl);
        }
        __syncthreads();
        #pragma unroll
        for (int pass = 0; pass < 3; pass++) {
            const uint32_t Ab = (pass == 2) ? sAl : sAh;
            const uint32_t Bb = (pass == 1) ? sBl : sBh;
            #pragma unroll
            for (int kt = 0; kt < kKC / 16; kt++) {
                uint32_t a[2][4];
                #pragma unroll
                for (int mi = 0; mi < 2; mi++) {
                    int row = wm * 32 + mi * 16 + aRowL;
                    ldsm_x4(a[mi], Ab + swz(row * 128 + (kt * 16 + aKoffL) * 2));
                }
                uint32_t b[10][2];
                #pragma unroll
                for (int bi = 0; bi < 5; bi++) {
                    int row = wn * 80 + bi * 16 + bRowL;
                    uint32_t r[4];
                    ldsm_x4(r, Bb + swz(row * 128 + (kt * 16 + bKoffL) * 2));
                    b[2*bi][0] = r[0]; b[2*bi][1] = r[1];
                    b[2*bi+1][0] = r[2]; b[2*bi+1][1] = r[3];
                }
                #pragma unroll
                for (int mi = 0; mi < 2; mi++)
                    #pragma unroll
                    for (int ni = 0; ni < 10; ni++)
                        mma16816(acc[mi][ni], a[mi], b[ni]);
            }
        }
        __syncthreads();
    }
    const float sc = 1.0f / sqrtf((float)kD);
    float* C = d_attn + (size_t)c * kQR * kKUP;
    const int colB = wn * 80 + (lane & 3) * 2;
    #pragma unroll
    for (int mi = 0; mi < 2; mi++) {
        int row0 = bm + wm * 32 + mi * 16 + (lane >> 2);
        #pragma unroll
        for (int ni = 0; ni < 10; ni++) {
            int col = colB + ni * 8;
            if (col < kKUP) {
                if (row0 < kQR)
                    *(float2*)(C + (size_t)row0 * kKUP + col) =
                        make_float2(acc[mi][ni][0] * sc, acc[mi][ni][1] * sc);
                if (row0 + 8 < kQR)
                    *(float2*)(C + (size_t)(row0 + 8) * kKUP + col) =
                        make_float2(acc[mi][ni][2] * sc, acc[mi][ni][3] * sc);
            }
        }
    }
}

// ---------------- K4: softmax -> attn hi/lo bf16 (zero-padded to 144) ----------------
__global__ void k_softmax() {
    int row = (blockIdx.x << 3) + (threadIdx.x >> 5);   // 70000 rows
    int lane = threadIdx.x & 31;
    const float* p = d_attn + (size_t)row * kKUP;
    float v[5];
    float m = -1e30f;
    #pragma unroll
    for (int u = 0; u < 5; u++) {
        int i = lane + (u << 5);
        v[u] = (i < kKU) ? p[i] : -1e30f;
        m = fmaxf(m, v[u]);
    }
    #pragma unroll
    for (int o = 16; o; o >>= 1) m = fmaxf(m, __shfl_xor_sync(0xffffffffu, m, o));
    float s = 0.f;
    #pragma unroll
    for (int u = 0; u < 5; u++) {
        float e = ((lane + (u << 5)) < kKU) ? expf(v[u] - m) : 0.f;
        v[u] = e; s += e;
    }
    #pragma unroll
    for (int o = 16; o; o >>= 1) s += __shfl_xor_sync(0xffffffffu, s, o);
    float inv = 1.0f / s;
    #pragma unroll
    for (int u = 0; u < 5; u++) {
        int i = lane + (u << 5);
        if (i < kKUP) {
            float a = (i < kKU) ? v[u] * inv : 0.f;
            __nv_bfloat16 h = __float2bfloat16(a);
            d_ATh[(size_t)row * kKUP + i] = h;
            d_ATl[(size_t)row * kKUP + i] = __float2bfloat16(a - __bfloat162float(h));
        }
    }
}

// ---------------- K5a: zero dist accumulators ----------------
__global__ void k_zero() {
    int i = blockIdx.x * blockDim.x + threadIdx.x;
    if (i < kWAY * kNQ) d_distq[i] = 0.f;
}

// ---------------- K5: proto via HMMA + fused squared-distance ----------------
// grid (mtile 110, dtile 9, c 5). CTA: 128 q-rows x 128 D-cols, K=144 (pad->192).
__global__ __launch_bounds__(256) void k_dist_mma() {
    extern __shared__ __align__(16) char dsm[];
    const uint32_t sb = smem_u32(dsm);
    const uint32_t sAh = sb, sAl = sb + 16384, sBh = sb + 32768, sBl = sb + 49152;
    const int tid = threadIdx.x;
    const int wid = tid >> 5, lane = tid & 31;
    const int wm = wid >> 2, wn = wid & 3;
    const int bm = blockIdx.x * 128;
    const int bn = blockIdx.y * 128;
    const int c  = blockIdx.z;

    float acc[4][4][4];
    #pragma unroll
    for (int mi = 0; mi < 4; mi++)
        #pragma unroll
        for (int ni = 0; ni < 4; ni++)
            #pragma unroll
            for (int e = 0; e < 4; e++) acc[mi][ni][e] = 0.f;

    const int aRowL = (lane & 15);
    const int aKoffL = (lane >> 4) << 3;
    const int bGrp  = lane >> 3;
    const int bRowL = ((bGrp >> 1) << 3) + (lane & 7);
    const int bKoffL = (bGrp & 1) << 3;

    const __nv_bfloat16* ATh = d_ATh + ((size_t)c * kQR) * kKUP;
    const __nv_bfloat16* ATl = d_ATl + ((size_t)c * kQR) * kKUP;
    const __nv_bfloat16* VTh = d_VTh + ((size_t)c * kD) * kKUP;
    const __nv_bfloat16* VTl = d_VTl + ((size_t)c * kD) * kKUP;

    for (int kc = 0; kc < 192; kc += kKC) {
        #pragma unroll
        for (int j = 0; j < 4; j++) {               // A: attn 128 rows x 64 k
            int u = tid + j * 256;
            int row = u >> 3, bc = (u & 7) << 4;
            int e0 = kc + (bc >> 1);
            uint4 vh = make_uint4(0u,0u,0u,0u), vl = make_uint4(0u,0u,0u,0u);
            if (e0 < kKUP && bm + row < kQR) {
                size_t go = (size_t)(bm + row) * kKUP + e0;
                vh = *(const uint4*)(ATh + go); vl = *(const uint4*)(ATl + go);
            }
            uint32_t so = swz(row * 128 + bc);
            st128s(sAh + so, vh);
            st128s(sAl + so, vl);
        }
        #pragma unroll
        for (int j = 0; j < 4; j++) {               // B: VT 128 D-rows x 64 k
            int u = tid + j * 256;
            int row = u >> 3, bc = (u & 7) << 4;
            int e0 = kc + (bc >> 1);
            uint4 vh = make_uint4(0u,0u,0u,0u), vl = make_uint4(0u,0u,0u,0u);
            if (e0 < kKUP) {
                size_t go = (size_t)(bn + row) * kKUP + e0;
                vh = *(const uint4*)(VTh + go); vl = *(const uint4*)(VTl + go);
            }
            uint32_t so = swz(row * 128 + bc);
            st128s(sBh + so, vh);
            st128s(sBl + so, vl);
        }
        __syncthreads();
        #pragma unroll
        for (int pass = 0; pass < 3; pass++) {
            const uint32_t Ab = (pass == 2) ? sAl : sAh;
            const uint32_t Bb = (pass == 1) ? sBl : sBh;
            #pragma unroll
            for (int kt = 0; kt < kKC / 16; kt++) {
                uint32_t a[4][4];
                #pragma unroll
                for (int mi = 0; mi < 4; mi++) {
                    int row = wm * 64 + mi * 16 + aRowL;
                    ldsm_x4(a[mi], Ab + swz(row * 128 + (kt * 16 + aKoffL) * 2));
                }
                uint32_t b[4][2];
                #pragma unroll
                for (int bi = 0; bi < 2; bi++) {
                    int row = wn * 32 + bi * 16 + bRowL;
                    uint32_t r[4];
                    ldsm_x4(r, Bb + swz(row * 128 + (kt * 16 + bKoffL) * 2));
                    b[2*bi][0] = r[0]; b[2*bi][1] = r[1];
                    b[2*bi+1][0] = r[2]; b[2*bi+1][1] = r[3];
                }
                #pragma unroll
                for (int mi = 0; mi < 4; mi++)
                    #pragma unroll
                    for (int ni = 0; ni < 4; ni++)
                        mma16816(acc[mi][ni], a[mi], b[ni]);
            }
        }
        __syncthreads();
    }

    // fused epilogue: diff vs q_vs, square, reduce, atomicAdd per (c, q)
    const int colB = bn + wn * 32 + (lane & 3) * 2;
    #pragma unroll
    for (int mi = 0; mi < 4; mi++) {
        int r0 = bm + wm * 64 + mi * 16 + (lane >> 2);   // global q-row
        float s0 = 0.f, s1 = 0.f;
        #pragma unroll
        for (int ni = 0; ni < 4; ni++) {
            int col = colB + ni * 8;
            if (r0 < kQR) {
                float2 qa = *(const float2*)(d_qv + (size_t)(kNS * kT + r0) * kD + col);
                float d0 = qa.x - acc[mi][ni][0], d1 = qa.y - acc[mi][ni][1];
                s0 += d0 * d0 + d1 * d1;
            }
            if (r0 + 8 < kQR) {
                float2 qb = *(const float2*)(d_qv + (size_t)(kNS * kT + r0 + 8) * kD + col);
                float d2 = qb.x - acc[mi][ni][2], d3 = qb.y - acc[mi][ni][3];
                s1 += d2 * d2 + d3 * d3;
            }
        }
        s0 += __shfl_xor_sync(0xffffffffu, s0, 1);
        s0 += __shfl_xor_sync(0xffffffffu, s0, 2);
        s1 += __shfl_xor_sync(0xffffffffu, s1, 1);
        s1 += __shfl_xor_sync(0xffffffffu, s1, 2);
        if ((lane & 3) == 0) {
            if (r0 < kQR)     atomicAdd(&d_distq[c * kNQ + r0 / kT], s0);
            if (r0 + 8 < kQR) atomicAdd(&d_distq[c * kNQ + (r0 + 8) / kT], s1);
        }
    }
}

// ---------------- K6: logits ----------------
__global__ void k_logits(const float* __restrict__ gt, const float* __restrict__ tw,
                         float* __restrict__ out) {
    int i = blockIdx.x * blockDim.x + threadIdx.x;
    if (i < kWAY * kNQ) {
        int c = i / kNQ, q = i - c * kNQ;
        out[q * kWAY + c] = -(d_distq[i] / (float)kT) * gt[0] * tw[0];
    }
}

// ---------------- launch ----------------
extern "C" void kernel_launch(void* const* d_in, const int* in_sizes, int n_in,
                              void* d_out, int out_size) {
    const float* sup = (const float*)d_in[0];
    const float* qry = (const float*)d_in[2];
    const float* kw  = (const float*)d_in[3];
    const float* kb  = (const float*)d_in[4];
    const float* vw  = (const float*)d_in[5];
    const float* vb  = (const float*)d_in[6];
    const float* g   = (const float*)d_in[7];
    const float* be  = (const float*)d_in[8];
    const float* gt  = (const float*)d_in[9];
    const float* tw  = (const float*)d_in[10];
    float* out = (float*)d_out;

    cudaFuncSetAttribute(k1_hmma, cudaFuncAttributeMaxDynamicSharedMemorySize, 65536);
    cudaFuncSetAttribute(k_scores_mma, cudaFuncAttributeMaxDynamicSharedMemorySize, 73728);
    cudaFuncSetAttribute(k_dist_mma, cudaFuncAttributeMaxDynamicSharedMemorySize, 65536);

    k_build_ax<<<kRX, 256>>>(sup, qry);
    k_split_b<<<dim3(kFEAT / 32, kPC / 32), dim3(32, 8)>>>(kw, vw);
    k1_hmma<<<dim3(kPC / 128, (kRX + 127) / 128), 256, 65536>>>();
    k_combine<<<kNTR, 256>>>(kb, vb, g, be);
    k_vt<<<dim3(5, kD / 32, kWAY), dim3(32, 8)>>>(0);
    k_scores_mma<<<dim3((kQR + 127) / 128, 1, kWAY), 256, 73728>>>();
    k_softmax<<<(kWAY * kQR) / 8, 256>>>();
    k_zero<<<(kWAY * kNQ + 255) / 256, 256>>>();
    k_dist_mma<<<dim3((kQR + 127) / 128, kD / 128, kWAY), 256, 65536>>>();
    k_logits<<<(kWAY * kNQ + 255) / 256, 256>>>(gt, tw, out);
}

// round 15
// speedup vs baseline: 15.5223x; 1.1349x over previous
#include <cuda_runtime.h>
#include <cuda_bf16.h>
#include <math.h>
#include <stdint.h>

// ---------------- problem constants ----------------
constexpr int kNS   = 25;
constexpr int kNQ   = 500;
constexpr int kNALL = kNS + kNQ;     // 525
constexpr int kSEQ  = 8;
constexpr int kFEAT = 2048;
constexpr int kD    = 1152;
constexpr int kT    = 28;
constexpr int kWAY  = 5;
constexpr int kKU   = 140;
constexpr int kKUP  = 144;
constexpr int kRX   = kNALL * kSEQ;  // 4200
constexpr int kPC   = 4 * kD;        // 4608
constexpr int kQR   = kNQ * kT;      // 14000
constexpr int kNTR  = kNALL * kT;    // 14700

// ---------------- scratch ----------------
__device__ float d_PE[kSEQ * kFEAT];
__device__ __nv_bfloat16 d_Ah[(size_t)kRX * kFEAT];
__device__ __nv_bfloat16 d_Al[(size_t)kRX * kFEAT];
__device__ __nv_bfloat16 d_Bh[(size_t)kPC * kFEAT];   // [4608 n][2048 k]
__device__ __nv_bfloat16 d_Bl[(size_t)kPC * kFEAT];
__device__ float d_P[(size_t)kRX * kPC];
__device__ __nv_bfloat16 d_Kh[(size_t)kNTR * kD];     // LN'd K, hi/lo
__device__ __nv_bfloat16 d_Kl[(size_t)kNTR * kD];
__device__ float d_qv[(size_t)kNTR * kD];             // V features fp32
__device__ float d_attn[(size_t)kWAY * kQR * kKUP];   // scores (fp32)
__device__ __nv_bfloat16 d_ATh[(size_t)kWAY * kQR * kKUP];  // attn hi/lo
__device__ __nv_bfloat16 d_ATl[(size_t)kWAY * kQR * kKUP];
__device__ __nv_bfloat16 d_VTh[(size_t)kWAY * kD * kKUP];   // support V^T hi/lo
__device__ __nv_bfloat16 d_VTl[(size_t)kWAY * kD * kKUP];
__device__ float d_distq[kWAY * kNQ];

__constant__ int c_ti[kT] = {0,0,0,0,0,0,0,1,1,1,1,1,1,2,2,2,2,2,3,3,3,3,4,4,4,5,5,6};
__constant__ int c_tj[kT] = {1,2,3,4,5,6,7,2,3,4,5,6,7,3,4,5,6,7,4,5,6,7,5,6,7,6,7,7};

// ---------------- smem / hmma / cp.async helpers ----------------
__device__ __forceinline__ uint32_t smem_u32(const void* p) {
    uint32_t a;
    asm("{ .reg .u64 t; cvta.to.shared.u64 t, %1; cvt.u32.u64 %0, t; }" : "=r"(a) : "l"(p));
    return a;
}
__device__ __forceinline__ uint32_t swz(uint32_t o) { return o ^ ((o >> 3) & 0x70); }
__device__ __forceinline__ void st128s(uint32_t a, uint4 v) {
    asm volatile("st.shared.v4.b32 [%0],{%1,%2,%3,%4};" :: "r"(a), "r"(v.x), "r"(v.y), "r"(v.z), "r"(v.w) : "memory");
}
__device__ __forceinline__ void ldsm_x4(uint32_t* r, uint32_t addr) {
    asm volatile("ldmatrix.sync.aligned.m8n8.x4.shared.b16 {%0,%1,%2,%3}, [%4];"
                 : "=r"(r[0]), "=r"(r[1]), "=r"(r[2]), "=r"(r[3]) : "r"(addr));
}
__device__ __forceinline__ void mma16816(float* d, const uint32_t* a, const uint32_t* b) {
    asm volatile(
        "mma.sync.aligned.m16n8k16.row.col.f32.bf16.bf16.f32 "
        "{%0,%1,%2,%3}, {%4,%5,%6,%7}, {%8,%9}, {%0,%1,%2,%3};"
        : "+f"(d[0]), "+f"(d[1]), "+f"(d[2]), "+f"(d[3])
        : "r"(a[0]), "r"(a[1]), "r"(a[2]), "r"(a[3]), "r"(b[0]), "r"(b[1]));
}
__device__ __forceinline__ void cp16(uint32_t s, const void* g) {
    asm volatile("cp.async.cg.shared.global [%0], [%1], 16;" :: "r"(s), "l"(g));
}
__device__ __forceinline__ void cp16z(uint32_t s, const void* g, unsigned sz) {
    asm volatile("cp.async.cg.shared.global [%0], [%1], 16, %2;" :: "r"(s), "l"(g), "r"(sz));
}
__device__ __forceinline__ void cp_commit() { asm volatile("cp.async.commit_group;" ::: "memory"); }
__device__ __forceinline__ void cp_wait1() { asm volatile("cp.async.wait_group 1;" ::: "memory"); }

// ---------------- K0pe: positional-encoding table ----------------
__global__ void k_pe() {
    int f = blockIdx.x;
    const float cc = -logf(10000.0f) / (float)kFEAT;
    float pf = (float)f;
    for (int d = threadIdx.x; d < kFEAT; d += blockDim.x) {
        int j2 = d & ~1;
        float v = pf * expf(cc * (float)j2);
        d_PE[f * kFEAT + d] = (d & 1) ? cosf(v) : sinf(v);
    }
}

// ---------------- K0a: frames + PE -> hi/lo bf16 ----------------
__global__ void k_build_ax(const float* __restrict__ sup, const float* __restrict__ qry) {
    int r = blockIdx.x;                 // 0..4199
    int n = r >> 3, f = r & 7;
    const float* src = (n < kNS) ? (sup + (size_t)r * kFEAT)
                                 : (qry + (size_t)(r - kNS * kSEQ) * kFEAT);
    const float* pe = d_PE + f * kFEAT;
    for (int d = threadIdx.x; d < kFEAT; d += blockDim.x) {
        float x = src[d] + pe[d];
        __nv_bfloat16 h = __float2bfloat16(x);
        d_Ah[(size_t)r * kFEAT + d] = h;
        d_Al[(size_t)r * kFEAT + d] = __float2bfloat16(x - __bfloat162float(h));
    }
}

// ---------------- K0b: transpose + hi/lo split of weights -> B[n][k] ----------------
__global__ void k_split_b(const float* __restrict__ kw, const float* __restrict__ vw) {
    __shared__ float tile[32][33];
    int kb = blockIdx.x * 32, nb = blockIdx.y * 32;
    int tx = threadIdx.x, ty = threadIdx.y;     // (32,8)
    int sel = nb / kD;
    const float* src = (sel < 2) ? kw : vw;
    int krow = kb + (sel & 1) * kFEAT;
    int col0 = nb % kD;
    #pragma unroll
    for (int i = 0; i < 4; i++)
        tile[ty + 8*i][tx] = src[(size_t)(krow + ty + 8*i) * kD + col0 + tx];
    __syncthreads();
    #pragma unroll
    for (int i = 0; i < 4; i++) {
        float x = tile[tx][ty + 8*i];
        __nv_bfloat16 h = __float2bfloat16(x);
        size_t o = (size_t)(nb + ty + 8*i) * kFEAT + kb + tx;
        d_Bh[o] = h;
        d_Bl[o] = __float2bfloat16(x - __bfloat162float(h));
    }
}

// ---------------- K1: split-bf16 HMMA GEMM with cp.async double buffering ----------------
constexpr int kKC = 64;
constexpr int kNCH = kFEAT / kKC;    // 32
__global__ __launch_bounds__(256) void k1_hmma() {
    extern __shared__ __align__(16) char dsm[];
    const uint32_t sb = smem_u32(dsm);   // [2][Ah 16K | Al 16K | Bh 16K | Bl 16K]
    const int tid  = threadIdx.x;
    const int wid  = tid >> 5, lane = tid & 31;
    const int wm   = wid >> 2, wn = wid & 3;
    const int bm   = blockIdx.y * 128;
    const int bn   = blockIdx.x * 128;

    // per-thread staging geometry (4 units per tile)
    int srow[4], sbc[4]; uint32_t soff[4];
    #pragma unroll
    for (int j = 0; j < 4; j++) {
        int u = tid + j * 256;
        srow[j] = u >> 3; sbc[j] = (u & 7) << 4;
        soff[j] = swz(srow[j] * 128 + sbc[j]);
    }

    float acc[4][4][4];
    #pragma unroll
    for (int mi = 0; mi < 4; mi++)
        #pragma unroll
        for (int ni = 0; ni < 4; ni++)
            #pragma unroll
            for (int e = 0; e < 4; e++) acc[mi][ni][e] = 0.f;

    const int aRowL = (lane & 15);
    const int aKoffL = (lane >> 4) << 3;
    const int bGrp  = lane >> 3;
    const int bRowL = ((bGrp >> 1) << 3) + (lane & 7);
    const int bKoffL = (bGrp & 1) << 3;

    auto stage = [&](int c) {
        const uint32_t base = sb + (uint32_t)(c & 1) * 65536u;
        const int kc = c * kKC;
        #pragma unroll
        for (int j = 0; j < 4; j++) {
            int gr = bm + srow[j];
            int grc = (gr < kRX) ? gr : 0;
            unsigned sz = (gr < kRX) ? 16u : 0u;
            size_t goA = (size_t)grc * kFEAT + kc + (sbc[j] >> 1);
            cp16z(base + soff[j],          d_Ah + goA, sz);
            cp16z(base + 16384 + soff[j],  d_Al + goA, sz);
            size_t goB = (size_t)(bn + srow[j]) * kFEAT + kc + (sbc[j] >> 1);
            cp16(base + 32768 + soff[j],   d_Bh + goB);
            cp16(base + 49152 + soff[j],   d_Bl + goB);
        }
    };

    stage(0);
    cp_commit();

    for (int c = 0; c < kNCH; c++) {
        if (c + 1 < kNCH) stage(c + 1);
        cp_commit();
        cp_wait1();
        __syncthreads();
        const uint32_t bufb = sb + (uint32_t)(c & 1) * 65536u;
        #pragma unroll
        for (int pass = 0; pass < 3; pass++) {
            const uint32_t Ab = bufb + ((pass == 2) ? 16384u : 0u);
            const uint32_t Bb = bufb + ((pass == 1) ? 49152u : 32768u);
            #pragma unroll
            for (int kt = 0; kt < kKC / 16; kt++) {
                uint32_t a[4][4];
                #pragma unroll
                for (int mi = 0; mi < 4; mi++) {
                    int row = wm * 64 + mi * 16 + aRowL;
                    ldsm_x4(a[mi], Ab + swz(row * 128 + (kt * 16 + aKoffL) * 2));
                }
                uint32_t b[4][2];
                #pragma unroll
                for (int bi = 0; bi < 2; bi++) {
                    int row = wn * 32 + bi * 16 + bRowL;
                    uint32_t r[4];
                    ldsm_x4(r, Bb + swz(row * 128 + (kt * 16 + bKoffL) * 2));
                    b[2*bi][0] = r[0]; b[2*bi][1] = r[1];
                    b[2*bi+1][0] = r[2]; b[2*bi+1][1] = r[3];
                }
                #pragma unroll
                for (int mi = 0; mi < 4; mi++)
                    #pragma unroll
                    for (int ni = 0; ni < 4; ni++)
                        mma16816(acc[mi][ni], a[mi], b[ni]);
            }
        }
        __syncthreads();
    }

    const int colB = bn + wn * 32 + (lane & 3) * 2;
    #pragma unroll
    for (int mi = 0; mi < 4; mi++) {
        int row0 = bm + wm * 64 + mi * 16 + (lane >> 2);
        #pragma unroll
        for (int ni = 0; ni < 4; ni++) {
            int col = colB + ni * 8;
            if (row0 < kRX)
                *(float2*)(d_P + (size_t)row0 * kPC + col) = make_float2(acc[mi][ni][0], acc[mi][ni][1]);
            if (row0 + 8 < kRX)
                *(float2*)(d_P + (size_t)(row0 + 8) * kPC + col) = make_float2(acc[mi][ni][2], acc[mi][ni][3]);
        }
    }
}

// ---------------- K2: tuple combine + bias + LN(K) -> split bf16 K; fp32 V ----------------
__global__ __launch_bounds__(256) void k_combine(const float* __restrict__ kb,
                                                 const float* __restrict__ vb,
                                                 const float* __restrict__ g,
                                                 const float* __restrict__ be) {
    int b = blockIdx.x;
    int n = b / kT, t = b - n * kT;
    const float* Pi = d_P + (size_t)(n * kSEQ + c_ti[t]) * kPC;
    const float* Pj = d_P + (size_t)(n * kSEQ + c_tj[t]) * kPC;
    int tid = threadIdx.x;
    float kv[5];
    float s = 0.f, ss = 0.f;
    #pragma unroll
    for (int u = 0; u < 5; u++) {
        int d = tid + (u << 8);
        if (d < kD) {
            float val = Pi[d] + Pj[kD + d] + kb[d];
            kv[u] = val; s += val; ss += val * val;
            d_qv[(size_t)b * kD + d] = Pi[2*kD + d] + Pj[3*kD + d] + vb[d];
        }
    }
    #pragma unroll
    for (int o = 16; o; o >>= 1) {
        s  += __shfl_xor_sync(0xffffffffu, s, o);
        ss += __shfl_xor_sync(0xffffffffu, ss, o);
    }
    __shared__ float shs[8], shss[8];
    __shared__ float sh_mu, sh_inv;
    if ((tid & 31) == 0) { shs[tid >> 5] = s; shss[tid >> 5] = ss; }
    __syncthreads();
    if (tid == 0) {
        float S = 0.f, SS = 0.f;
        #pragma unroll
        for (int w = 0; w < 8; w++) { S += shs[w]; SS += shss[w]; }
        float mu = S / (float)kD;
        sh_mu = mu;
        sh_inv = rsqrtf(SS / (float)kD - mu * mu + 1e-5f);
    }
    __syncthreads();
    float mu = sh_mu, inv = sh_inv;
    #pragma unroll
    for (int u = 0; u < 5; u++) {
        int d = tid + (u << 8);
        if (d < kD) {
            float kn = (kv[u] - mu) * inv * g[d] + be[d];
            __nv_bfloat16 h = __float2bfloat16(kn);
            d_Kh[(size_t)b * kD + d] = h;
            d_Kl[(size_t)b * kD + d] = __float2bfloat16(kn - __bfloat162float(h));
        }
    }
}

// ---------------- K2b: transpose support V -> VT[c][d][u] hi/lo bf16 ----------------
__global__ void k_vt(int dummy) {
    __shared__ float t[32][33];
    int u0 = blockIdx.x * 32, d0 = blockIdx.y * 32, c = blockIdx.z;
    int tx = threadIdx.x, ty = threadIdx.y;     // (32,8)
    #pragma unroll
    for (int i = 0; i < 4; i++) {
        int u = u0 + ty + 8*i;
        t[ty + 8*i][tx] = (u < kKU) ? d_qv[((size_t)c * kKU + u) * kD + d0 + tx] : 0.f;
    }
    __syncthreads();
    #pragma unroll
    for (int i = 0; i < 4; i++) {
        int d = d0 + ty + 8*i;
        int u = u0 + tx;
        if (u < kKUP) {
            float x = t[tx][ty + 8*i];
            __nv_bfloat16 h = __float2bfloat16(x);
            size_t o = ((size_t)c * kD + d) * kKUP + u;
            d_VTh[o] = h;
            d_VTl[o] = __float2bfloat16(x - __bfloat162float(h));
        }
    }
}

// ---------------- K3: scores via split-bf16 HMMA ----------------
__global__ __launch_bounds__(256) void k_scores_mma() {
    extern __shared__ __align__(16) char dsm[];
    const uint32_t sb = smem_u32(dsm);
    const uint32_t sAh = sb, sAl = sb + 16384;
    const uint32_t sBh = sb + 32768, sBl = sb + 32768 + 20480;
    const int tid = threadIdx.x;
    const int wid = tid >> 5, lane = tid & 31;
    const int wm = wid >> 1, wn = wid & 1;
    const int c  = blockIdx.z;
    const int bm = blockIdx.x * 128;

    float acc[2][10][4];
    #pragma unroll
    for (int mi = 0; mi < 2; mi++)
        #pragma unroll
        for (int ni = 0; ni < 10; ni++)
            #pragma unroll
            for (int e = 0; e < 4; e++) acc[mi][ni][e] = 0.f;

    const int aRowL = (lane & 15);
    const int aKoffL = (lane >> 4) << 3;
    const int bGrp  = lane >> 3;
    const int bRowL = ((bGrp >> 1) << 3) + (lane & 7);
    const int bKoffL = (bGrp & 1) << 3;

    for (int kc = 0; kc < kD; kc += kKC) {
        #pragma unroll
        for (int j = 0; j < 4; j++) {
            int u = tid + j * 256;
            int row = u >> 3, bc = (u & 7) << 4;
            uint4 vh = make_uint4(0u,0u,0u,0u), vl = make_uint4(0u,0u,0u,0u);
            if (bm + row < kQR) {
                size_t go = (size_t)(kNS * kT + bm + row) * kD + kc + (bc >> 1);
                vh = *(const uint4*)(d_Kh + go); vl = *(const uint4*)(d_Kl + go);
            }
            uint32_t so = swz(row * 128 + bc);
            st128s(sAh + so, vh);
            st128s(sAl + so, vl);
        }
        #pragma unroll
        for (int j = 0; j < 5; j++) {
            int u = tid + j * 256;
            int row = u >> 3, bc = (u & 7) << 4;
            uint4 vh = make_uint4(0u,0u,0u,0u), vl = make_uint4(0u,0u,0u,0u);
            if (row < kKU) {
                size_t go = (size_t)(c * kKU + row) * kD + kc + (bc >> 1);
                vh = *(const uint4*)(d_Kh + go); vl = *(const uint4*)(d_Kl + go);
            }
            uint32_t so = swz(row * 128 + bc);
            st128s(sBh + so, vh);
            st128s(sBl + so, vl);
        }
        __syncthreads();
        #pragma unroll
        for (int pass = 0; pass < 3; pass++) {
            const uint32_t Ab = (pass == 2) ? sAl : sAh;
            const uint32_t Bb = (pass == 1) ? sBl : sBh;
            #pragma unroll
            for (int kt = 0; kt < kKC / 16; kt++) {
                uint32_t a[2][4];
                #pragma unroll
                for (int mi = 0; mi < 2; mi++) {
                    int row = wm * 32 + mi * 16 + aRowL;
                    ldsm_x4(a[mi], Ab + swz(row * 128 + (kt * 16 + aKoffL) * 2));
                }
                uint32_t b[10][2];
                #pragma unroll
                for (int bi = 0; bi < 5; bi++) {
                    int row = wn * 80 + bi * 16 + bRowL;
                    uint32_t r[4];
                    ldsm_x4(r, Bb + swz(row * 128 + (kt * 16 + bKoffL) * 2));
                    b[2*bi][0] = r[0]; b[2*bi][1] = r[1];
                    b[2*bi+1][0] = r[2]; b[2*bi+1][1] = r[3];
                }
                #pragma unroll
                for (int mi = 0; mi < 2; mi++)
                    #pragma unroll
                    for (int ni = 0; ni < 10; ni++)
                        mma16816(acc[mi][ni], a[mi], b[ni]);
            }
        }
        __syncthreads();
    }
    const float sc = 1.0f / sqrtf((float)kD);
    float* C = d_attn + (size_t)c * kQR * kKUP;
    const int colB = wn * 80 + (lane & 3) * 2;
    #pragma unroll
    for (int mi = 0; mi < 2; mi++) {
        int row0 = bm + wm * 32 + mi * 16 + (lane >> 2);
        #pragma unroll
        for (int ni = 0; ni < 10; ni++) {
            int col = colB + ni * 8;
            if (col < kKUP) {
                if (row0 < kQR)
                    *(float2*)(C + (size_t)row0 * kKUP + col) =
                        make_float2(acc[mi][ni][0] * sc, acc[mi][ni][1] * sc);
                if (row0 + 8 < kQR)
                    *(float2*)(C + (size_t)(row0 + 8) * kKUP + col) =
                        make_float2(acc[mi][ni][2] * sc, acc[mi][ni][3] * sc);
            }
        }
    }
}

// ---------------- K4: softmax -> attn hi/lo bf16 (zero-padded to 144) ----------------
__global__ void k_softmax() {
    int row = (blockIdx.x << 3) + (threadIdx.x >> 5);   // 70000 rows
    int lane = threadIdx.x & 31;
    const float* p = d_attn + (size_t)row * kKUP;
    float v[5];
    float m = -1e30f;
    #pragma unroll
    for (int u = 0; u < 5; u++) {
        int i = lane + (u << 5);
        v[u] = (i < kKU) ? p[i] : -1e30f;
        m = fmaxf(m, v[u]);
    }
    #pragma unroll
    for (int o = 16; o; o >>= 1) m = fmaxf(m, __shfl_xor_sync(0xffffffffu, m, o));
    float s = 0.f;
    #pragma unroll
    for (int u = 0; u < 5; u++) {
        float e = ((lane + (u << 5)) < kKU) ? __expf(v[u] - m) : 0.f;
        v[u] = e; s += e;
    }
    #pragma unroll
    for (int o = 16; o; o >>= 1) s += __shfl_xor_sync(0xffffffffu, s, o);
    float inv = 1.0f / s;
    #pragma unroll
    for (int u = 0; u < 5; u++) {
        int i = lane + (u << 5);
        if (i < kKUP) {
            float a = (i < kKU) ? v[u] * inv : 0.f;
            __nv_bfloat16 h = __float2bfloat16(a);
            d_ATh[(size_t)row * kKUP + i] = h;
            d_ATl[(size_t)row * kKUP + i] = __float2bfloat16(a - __bfloat162float(h));
        }
    }
}

// ---------------- K5a: zero dist accumulators ----------------
__global__ void k_zero() {
    int i = blockIdx.x * blockDim.x + threadIdx.x;
    if (i < kWAY * kNQ) d_distq[i] = 0.f;
}

// ---------------- K5: proto via HMMA + fused squared-distance ----------------
__global__ __launch_bounds__(256) void k_dist_mma() {
    extern __shared__ __align__(16) char dsm[];
    const uint32_t sb = smem_u32(dsm);
    const uint32_t sAh = sb, sAl = sb + 16384, sBh = sb + 32768, sBl = sb + 49152;
    const int tid = threadIdx.x;
    const int wid = tid >> 5, lane = tid & 31;
    const int wm = wid >> 2, wn = wid & 3;
    const int bm = blockIdx.x * 128;
    const int bn = blockIdx.y * 128;
    const int c  = blockIdx.z;

    float acc[4][4][4];
    #pragma unroll
    for (int mi = 0; mi < 4; mi++)
        #pragma unroll
        for (int ni = 0; ni < 4; ni++)
            #pragma unroll
            for (int e = 0; e < 4; e++) acc[mi][ni][e] = 0.f;

    const int aRowL = (lane & 15);
    const int aKoffL = (lane >> 4) << 3;
    const int bGrp  = lane >> 3;
    const int bRowL = ((bGrp >> 1) << 3) + (lane & 7);
    const int bKoffL = (bGrp & 1) << 3;

    const __nv_bfloat16* ATh = d_ATh + ((size_t)c * kQR) * kKUP;
    const __nv_bfloat16* ATl = d_ATl + ((size_t)c * kQR) * kKUP;
    const __nv_bfloat16* VTh = d_VTh + ((size_t)c * kD) * kKUP;
    const __nv_bfloat16* VTl = d_VTl + ((size_t)c * kD) * kKUP;

    for (int kc = 0; kc < 192; kc += kKC) {
        #pragma unroll
        for (int j = 0; j < 4; j++) {
            int u = tid + j * 256;
            int row = u >> 3, bc = (u & 7) << 4;
            int e0 = kc + (bc >> 1);
            uint4 vh = make_uint4(0u,0u,0u,0u), vl = make_uint4(0u,0u,0u,0u);
            if (e0 < kKUP && bm + row < kQR) {
                size_t go = (size_t)(bm + row) * kKUP + e0;
                vh = *(const uint4*)(ATh + go); vl = *(const uint4*)(ATl + go);
            }
            uint32_t so = swz(row * 128 + bc);
            st128s(sAh + so, vh);
            st128s(sAl + so, vl);
        }
        #pragma unroll
        for (int j = 0; j < 4; j++) {
            int u = tid + j * 256;
            int row = u >> 3, bc = (u & 7) << 4;
            int e0 = kc + (bc >> 1);
            uint4 vh = make_uint4(0u,0u,0u,0u), vl = make_uint4(0u,0u,0u,0u);
            if (e0 < kKUP) {
                size_t go = (size_t)(bn + row) * kKUP + e0;
                vh = *(const uint4*)(VTh + go); vl = *(const uint4*)(VTl + go);
            }
            uint32_t so = swz(row * 128 + bc);
            st128s(sBh + so, vh);
            st128s(sBl + so, vl);
        }
        __syncthreads();
        #pragma unroll
        for (int pass = 0; pass < 3; pass++) {
            const uint32_t Ab = (pass == 2) ? sAl : sAh;
            const uint32_t Bb = (pass == 1) ? sBl : sBh;
            #pragma unroll
            for (int kt = 0; kt < kKC / 16; kt++) {
                uint32_t a[4][4];
                #pragma unroll
                for (int mi = 0; mi < 4; mi++) {
                    int row = wm * 64 + mi * 16 + aRowL;
                    ldsm_x4(a[mi], Ab + swz(row * 128 + (kt * 16 + aKoffL) * 2));
                }
                uint32_t b[4][2];
                #pragma unroll
                for (int bi = 0; bi < 2; bi++) {
                    int row = wn * 32 + bi * 16 + bRowL;
                    uint32_t r[4];
                    ldsm_x4(r, Bb + swz(row * 128 + (kt * 16 + bKoffL) * 2));
                    b[2*bi][0] = r[0]; b[2*bi][1] = r[1];
                    b[2*bi+1][0] = r[2]; b[2*bi+1][1] = r[3];
                }
                #pragma unroll
                for (int mi = 0; mi < 4; mi++)
                    #pragma unroll
                    for (int ni = 0; ni < 4; ni++)
                        mma16816(acc[mi][ni], a[mi], b[ni]);
            }
        }
        __syncthreads();
    }

    const int colB = bn + wn * 32 + (lane & 3) * 2;
    #pragma unroll
    for (int mi = 0; mi < 4; mi++) {
        int r0 = bm + wm * 64 + mi * 16 + (lane >> 2);   // global q-row
        float s0 = 0.f, s1 = 0.f;
        #pragma unroll
        for (int ni = 0; ni < 4; ni++) {
            int col = colB + ni * 8;
            if (r0 < kQR) {
                float2 qa = *(const float2*)(d_qv + (size_t)(kNS * kT + r0) * kD + col);
                float d0 = qa.x - acc[mi][ni][0], d1 = qa.y - acc[mi][ni][1];
                s0 += d0 * d0 + d1 * d1;
            }
            if (r0 + 8 < kQR) {
                float2 qb = *(const float2*)(d_qv + (size_t)(kNS * kT + r0 + 8) * kD + col);
                float d2 = qb.x - acc[mi][ni][2], d3 = qb.y - acc[mi][ni][3];
                s1 += d2 * d2 + d3 * d3;
            }
        }
        s0 += __shfl_xor_sync(0xffffffffu, s0, 1);
        s0 += __shfl_xor_sync(0xffffffffu, s0, 2);
        s1 += __shfl_xor_sync(0xffffffffu, s1, 1);
        s1 += __shfl_xor_sync(0xffffffffu, s1, 2);
        if ((lane & 3) == 0) {
            if (r0 < kQR)     atomicAdd(&d_distq[c * kNQ + r0 / kT], s0);
            if (r0 + 8 < kQR) atomicAdd(&d_distq[c * kNQ + (r0 + 8) / kT], s1);
        }
    }
}

// ---------------- K6: logits ----------------
__global__ void k_logits(const float* __restrict__ gt, const float* __restrict__ tw,
                         float* __restrict__ out) {
    int i = blockIdx.x * blockDim.x + threadIdx.x;
    if (i < kWAY * kNQ) {
        int c = i / kNQ, q = i - c * kNQ;
        out[q * kWAY + c] = -(d_distq[i] / (float)kT) * gt[0] * tw[0];
    }
}

// ---------------- launch ----------------
extern "C" void kernel_launch(void* const* d_in, const int* in_sizes, int n_in,
                              void* d_out, int out_size) {
    const float* sup = (const float*)d_in[0];
    const float* qry = (const float*)d_in[2];
    const float* kw  = (const float*)d_in[3];
    const float* kb  = (const float*)d_in[4];
    const float* vw  = (const float*)d_in[5];
    const float* vb  = (const float*)d_in[6];
    const float* g   = (const float*)d_in[7];
    const float* be  = (const float*)d_in[8];
    const float* gt  = (const float*)d_in[9];
    const float* tw  = (const float*)d_in[10];
    float* out = (float*)d_out;

    cudaFuncSetAttribute(k1_hmma, cudaFuncAttributeMaxDynamicSharedMemorySize, 131072);
    cudaFuncSetAttribute(k_scores_mma, cudaFuncAttributeMaxDynamicSharedMemorySize, 73728);
    cudaFuncSetAttribute(k_dist_mma, cudaFuncAttributeMaxDynamicSharedMemorySize, 65536);

    k_pe<<<kSEQ, 256>>>();
    k_build_ax<<<kRX, 256>>>(sup, qry);
    k_split_b<<<dim3(kFEAT / 32, kPC / 32), dim3(32, 8)>>>(kw, vw);
    k1_hmma<<<dim3(kPC / 128, (kRX + 127) / 128), 256, 131072>>>();
    k_combine<<<kNTR, 256>>>(kb, vb, g, be);
    k_vt<<<dim3(5, kD / 32, kWAY), dim3(32, 8)>>>(0);
    k_scores_mma<<<dim3((kQR + 127) / 128, 1, kWAY), 256, 73728>>>();
    k_softmax<<<(kWAY * kQR) / 8, 256>>>();
    k_zero<<<(kWAY * kNQ + 255) / 256, 256>>>();
    k_dist_mma<<<dim3((kQR + 127) / 128, kD / 128, kWAY), 256, 65536>>>();
    k_logits<<<(kWAY * kNQ + 255) / 256, 256>>>(gt, tw, out);
}